// round 1
// baseline (speedup 1.0000x reference)
#include <cuda_runtime.h>
#include <cuda_bf16.h>
#include <mma.h>
#include <math.h>

using namespace nvcuda;

// Problem constants (shapes fixed by setup_inputs)
#define BATCH 4
#define SEQ   2048
#define CH    1024
#define NHEAD 16
#define DK    64
#define C3    3072
#define ROWS  (BATCH*SEQ)   // 8192

// ---------------- scratch ----------------
__device__ float g_qkv[(size_t)ROWS * C3];   // 96 MB
__device__ float g_attn[(size_t)ROWS * CH];  // 32 MB

// ---------------- TF32 wmma GEMM: C = A[MxK] * B[KxN] ----------------
#define TM 128
#define TN 128
#define TK 16
#define AS_LD 20
#define BS_LD 132

__global__ void __launch_bounds__(256) gemm_tf32_kernel(
    const float* __restrict__ A, const float* __restrict__ B,
    float* __restrict__ C, int M, int N, int K)
{
    __shared__ float As[TM * AS_LD];
    __shared__ float Bs[TK * BS_LD];

    const int tid = threadIdx.x;
    const int m0 = blockIdx.y * TM;
    const int n0 = blockIdx.x * TN;
    const int wid = tid >> 5;
    const int wm = wid & 3;   // 0..3 -> 32-row strip
    const int wn = wid >> 2;  // 0..1 -> 64-col strip

    wmma::fragment<wmma::accumulator, 16, 16, 8, float> acc[2][4];
    #pragma unroll
    for (int i = 0; i < 2; i++)
        #pragma unroll
        for (int j = 0; j < 4; j++)
            wmma::fill_fragment(acc[i][j], 0.0f);

    for (int k0 = 0; k0 < K; k0 += TK) {
        // A tile: 128 x 16  (512 float4 / 256 threads)
        #pragma unroll
        for (int f = tid; f < (TM * TK) / 4; f += 256) {
            int row = f >> 2;
            int c4  = (f & 3) << 2;
            float4 v = *reinterpret_cast<const float4*>(A + (size_t)(m0 + row) * K + k0 + c4);
            *reinterpret_cast<float4*>(As + row * AS_LD + c4) = v;
        }
        // B tile: 16 x 128
        #pragma unroll
        for (int f = tid; f < (TK * TN) / 4; f += 256) {
            int row = f >> 5;
            int c4  = (f & 31) << 2;
            float4 v = *reinterpret_cast<const float4*>(B + (size_t)(k0 + row) * N + n0 + c4);
            *reinterpret_cast<float4*>(Bs + row * BS_LD + c4) = v;
        }
        __syncthreads();

        #pragma unroll
        for (int kk = 0; kk < TK; kk += 8) {
            wmma::fragment<wmma::matrix_a, 16, 16, 8, wmma::precision::tf32, wmma::row_major> a[2];
            wmma::fragment<wmma::matrix_b, 16, 16, 8, wmma::precision::tf32, wmma::row_major> b[4];
            #pragma unroll
            for (int i = 0; i < 2; i++) {
                wmma::load_matrix_sync(a[i], As + (wm * 32 + i * 16) * AS_LD + kk, AS_LD);
                #pragma unroll
                for (int e = 0; e < a[i].num_elements; e++)
                    a[i].x[e] = wmma::__float_to_tf32(a[i].x[e]);
            }
            #pragma unroll
            for (int j = 0; j < 4; j++) {
                wmma::load_matrix_sync(b[j], Bs + kk * BS_LD + wn * 64 + j * 16, BS_LD);
                #pragma unroll
                for (int e = 0; e < b[j].num_elements; e++)
                    b[j].x[e] = wmma::__float_to_tf32(b[j].x[e]);
            }
            #pragma unroll
            for (int i = 0; i < 2; i++)
                #pragma unroll
                for (int j = 0; j < 4; j++)
                    wmma::mma_sync(acc[i][j], a[i], b[j], acc[i][j]);
        }
        __syncthreads();
    }

    #pragma unroll
    for (int i = 0; i < 2; i++)
        #pragma unroll
        for (int j = 0; j < 4; j++)
            wmma::store_matrix_sync(C + (size_t)(m0 + wm * 32 + i * 16) * N + n0 + wn * 64 + j * 16,
                                    acc[i][j], N, wmma::mem_row_major);
}

// ---------------- Flash attention (fp32 softmax, tf32 wmma GEMMs) ----------------
#define BQ 64
#define SLD 68   // 64 + 4 pad (272 B, 16B multiple)

// smem: Qs,Ks,Vs,Ss,Os,Ts (each 64*68) + m,l,alpha (each 64)
#define ATTN_SMEM_FLOATS (6 * BQ * SLD + 3 * BQ)
#define ATTN_SMEM_BYTES  (ATTN_SMEM_FLOATS * 4)

__global__ void __launch_bounds__(128) attn_kernel(
    const float* __restrict__ qkv, float* __restrict__ out)
{
    extern __shared__ float sm[];
    float* Qs = sm;
    float* Ks = Qs + BQ * SLD;
    float* Vs = Ks + BQ * SLD;
    float* Ss = Vs + BQ * SLD;  // reused as P
    float* Os = Ss + BQ * SLD;
    float* Ts = Os + BQ * SLD;
    float* mrow = Ts + BQ * SLD;
    float* lrow = mrow + BQ;
    float* arow = lrow + BQ;

    const int tid = threadIdx.x;
    const int wid = tid >> 5;
    const int qt = blockIdx.x;            // q tile 0..31
    const int bh = blockIdx.y;            // b*NHEAD + h
    const int b = bh >> 4;
    const int h = bh & 15;
    const float scale = 0.125f;           // 1/sqrt(64)

    // Load Q tile (pre-scaled)
    #pragma unroll
    for (int f = tid; f < (BQ * DK) / 4; f += 128) {
        int r = f >> 4;
        int c4 = (f & 15) << 2;
        const float* p = qkv + (size_t)(b * SEQ + qt * BQ + r) * C3 + h * DK + c4;
        float4 v = *reinterpret_cast<const float4*>(p);
        v.x *= scale; v.y *= scale; v.z *= scale; v.w *= scale;
        *reinterpret_cast<float4*>(Qs + r * SLD + c4) = v;
    }
    for (int f = tid; f < BQ * SLD; f += 128) Os[f] = 0.0f;
    if (tid < BQ) { mrow[tid] = -INFINITY; lrow[tid] = 0.0f; }
    __syncthreads();

    for (int j = 0; j <= qt; j++) {
        // Load K and V tiles
        #pragma unroll
        for (int f = tid; f < (BQ * DK) / 4; f += 128) {
            int r = f >> 4;
            int c4 = (f & 15) << 2;
            size_t base = (size_t)(b * SEQ + j * BQ + r) * C3 + h * DK + c4;
            *reinterpret_cast<float4*>(Ks + r * SLD + c4) =
                *reinterpret_cast<const float4*>(qkv + base + CH);
            *reinterpret_cast<float4*>(Vs + r * SLD + c4) =
                *reinterpret_cast<const float4*>(qkv + base + 2 * CH);
        }
        __syncthreads();

        // S = Q * K^T   (each warp: 16 q-rows x 64 keys)
        {
            wmma::fragment<wmma::accumulator, 16, 16, 8, float> c[4];
            #pragma unroll
            for (int n = 0; n < 4; n++) wmma::fill_fragment(c[n], 0.0f);
            #pragma unroll
            for (int kk = 0; kk < DK; kk += 8) {
                wmma::fragment<wmma::matrix_a, 16, 16, 8, wmma::precision::tf32, wmma::row_major> a;
                wmma::load_matrix_sync(a, Qs + (wid * 16) * SLD + kk, SLD);
                #pragma unroll
                for (int e = 0; e < a.num_elements; e++) a.x[e] = wmma::__float_to_tf32(a.x[e]);
                #pragma unroll
                for (int n = 0; n < 4; n++) {
                    wmma::fragment<wmma::matrix_b, 16, 16, 8, wmma::precision::tf32, wmma::col_major> bf;
                    wmma::load_matrix_sync(bf, Ks + (n * 16) * SLD + kk, SLD);
                    #pragma unroll
                    for (int e = 0; e < bf.num_elements; e++) bf.x[e] = wmma::__float_to_tf32(bf.x[e]);
                    wmma::mma_sync(c[n], a, bf, c[n]);
                }
            }
            #pragma unroll
            for (int n = 0; n < 4; n++)
                wmma::store_matrix_sync(Ss + (wid * 16) * SLD + n * 16, c[n], SLD, wmma::mem_row_major);
        }
        __syncthreads();

        // Online softmax: one thread per q row
        if (tid < BQ) {
            const int r = tid;
            const int nvalid = (j < qt) ? BQ : (r + 1);   // causal mask on diagonal tile
            float mo = mrow[r];
            float mx = mo;
            for (int c = 0; c < nvalid; c++) mx = fmaxf(mx, Ss[r * SLD + c]);
            float al = __expf(mo - mx);
            float s = 0.0f;
            for (int c = 0; c < nvalid; c++) {
                float p = __expf(Ss[r * SLD + c] - mx);
                Ss[r * SLD + c] = p;
                s += p;
            }
            for (int c = nvalid; c < BQ; c++) Ss[r * SLD + c] = 0.0f;
            mrow[r] = mx;
            lrow[r] = lrow[r] * al + s;
            arow[r] = al;
        }
        __syncthreads();

        // Ts = P * V
        {
            wmma::fragment<wmma::accumulator, 16, 16, 8, float> c[4];
            #pragma unroll
            for (int n = 0; n < 4; n++) wmma::fill_fragment(c[n], 0.0f);
            #pragma unroll
            for (int kk = 0; kk < BQ; kk += 8) {
                wmma::fragment<wmma::matrix_a, 16, 16, 8, wmma::precision::tf32, wmma::row_major> a;
                wmma::load_matrix_sync(a, Ss + (wid * 16) * SLD + kk, SLD);
                #pragma unroll
                for (int e = 0; e < a.num_elements; e++) a.x[e] = wmma::__float_to_tf32(a.x[e]);
                #pragma unroll
                for (int n = 0; n < 4; n++) {
                    wmma::fragment<wmma::matrix_b, 16, 16, 8, wmma::precision::tf32, wmma::row_major> bf;
                    wmma::load_matrix_sync(bf, Vs + kk * SLD + n * 16, SLD);
                    #pragma unroll
                    for (int e = 0; e < bf.num_elements; e++) bf.x[e] = wmma::__float_to_tf32(bf.x[e]);
                    wmma::mma_sync(c[n], a, bf, c[n]);
                }
            }
            #pragma unroll
            for (int n = 0; n < 4; n++)
                wmma::store_matrix_sync(Ts + (wid * 16) * SLD + n * 16, c[n], SLD, wmma::mem_row_major);
        }
        __syncthreads();

        // O = O * alpha + Ts
        #pragma unroll
        for (int f = tid; f < BQ * DK; f += 128) {
            int r = f >> 6;
            int c = f & 63;
            Os[r * SLD + c] = Os[r * SLD + c] * arow[r] + Ts[r * SLD + c];
        }
        __syncthreads();
    }

    // Write O / l  -> attn output laid out [B*T, C] with head offset
    #pragma unroll
    for (int f = tid; f < BQ * DK; f += 128) {
        int r = f >> 6;
        int c = f & 63;
        out[(size_t)(b * SEQ + qt * BQ + r) * CH + h * DK + c] = Os[r * SLD + c] / lrow[r];
    }
}

// ---------------- launch ----------------
extern "C" void kernel_launch(void* const* d_in, const int* in_sizes, int n_in,
                              void* d_out, int out_size)
{
    const float* x     = (const float*)d_in[0];   // [4,2048,1024]
    const float* w_qkv = (const float*)d_in[1];   // [1024,3072]
    const float* w_out = (const float*)d_in[2];   // [1024,1024]
    float* out = (float*)d_out;                   // [4,2048,1024]

    float* qkv = nullptr;
    float* att = nullptr;
    cudaGetSymbolAddress((void**)&qkv, g_qkv);
    cudaGetSymbolAddress((void**)&att, g_attn);

    cudaFuncSetAttribute(attn_kernel, cudaFuncAttributeMaxDynamicSharedMemorySize, ATTN_SMEM_BYTES);

    // 1) qkv = x @ w_qkv   [8192 x 3072]
    {
        dim3 grid(C3 / TN, ROWS / TM);
        gemm_tf32_kernel<<<grid, 256>>>(x, w_qkv, qkv, ROWS, C3, CH);
    }
    // 2) flash attention per (b,h,q-tile)
    {
        dim3 grid(SEQ / BQ, BATCH * NHEAD);
        attn_kernel<<<grid, 128, ATTN_SMEM_BYTES>>>(qkv, att);
    }
    // 3) out = attn @ w_out  [8192 x 1024]
    {
        dim3 grid(CH / TN, ROWS / TM);
        gemm_tf32_kernel<<<grid, 256>>>(att, w_out, out, ROWS, CH, CH);
    }
}

// round 2
// speedup vs baseline: 1.0690x; 1.0690x over previous
#include <cuda_runtime.h>
#include <cuda_bf16.h>
#include <mma.h>
#include <math.h>

using namespace nvcuda;

#define BATCH 4
#define SEQ   2048
#define CH    1024
#define NHEAD 16
#define DK    64
#define C3    3072
#define ROWS  (BATCH*SEQ)   // 8192

// ---------------- scratch ----------------
__device__ float g_qkv[(size_t)ROWS * C3];   // 96 MB
__device__ float g_attn[(size_t)ROWS * CH];  // 32 MB

// ---------------- cp.async helpers ----------------
__device__ __forceinline__ void cp_async16(void* smem_dst, const void* gmem_src) {
    unsigned s = (unsigned)__cvta_generic_to_shared(smem_dst);
    asm volatile("cp.async.cg.shared.global [%0], [%1], 16;\n" :: "r"(s), "l"(gmem_src));
}
__device__ __forceinline__ void cp_commit() {
    asm volatile("cp.async.commit_group;\n" ::);
}
template<int N>
__device__ __forceinline__ void cp_wait() {
    asm volatile("cp.async.wait_group %0;\n" :: "n"(N));
}

// ---------------- TF32 wmma GEMM: C = A[MxK] * B[KxN], 4-stage pipeline ----------------
#define TM 128
#define TN 128
#define TK 16
#define AS_LD 20
#define BS_LD 132
#define STAGES 4
#define STAGE_FLOATS (TM*AS_LD + TK*BS_LD)   // 4672
#define GEMM_SMEM_BYTES (STAGES * STAGE_FLOATS * 4)

__global__ void __launch_bounds__(256, 2) gemm_tf32_kernel(
    const float* __restrict__ A, const float* __restrict__ B,
    float* __restrict__ C, int M, int N, int K)
{
    extern __shared__ float sm[];

    const int tid = threadIdx.x;
    const int m0 = blockIdx.y * TM;
    const int n0 = blockIdx.x * TN;
    const int wid = tid >> 5;
    const int wm = wid & 3;   // 0..3 -> 32-row strip
    const int wn = wid >> 2;  // 0..1 -> 64-col strip
    const int KT = K / TK;

    // per-thread load coordinates (2 A chunks + 2 B chunks of 16B each)
    const int ar0 = tid >> 2, ac0 = (tid & 3) << 2;          // A chunk 0: rows 0..63
    const int ar1 = (tid + 256) >> 2, ac1 = ac0;             // A chunk 1: rows 64..127
    const int br0 = tid >> 5, bc0 = (tid & 31) << 2;         // B chunk 0: rows 0..7
    const int br1 = (tid + 256) >> 5, bc1 = bc0;             // B chunk 1: rows 8..15

    auto load_tile = [&](int buf, int kt) {
        float* As = sm + buf * STAGE_FLOATS;
        float* Bs = As + TM * AS_LD;
        const int k0 = kt * TK;
        cp_async16(As + ar0 * AS_LD + ac0, A + (size_t)(m0 + ar0) * K + k0 + ac0);
        cp_async16(As + ar1 * AS_LD + ac1, A + (size_t)(m0 + ar1) * K + k0 + ac1);
        cp_async16(Bs + br0 * BS_LD + bc0, B + (size_t)(k0 + br0) * N + n0 + bc0);
        cp_async16(Bs + br1 * BS_LD + bc1, B + (size_t)(k0 + br1) * N + n0 + bc1);
    };

    wmma::fragment<wmma::accumulator, 16, 16, 8, float> acc[2][4];
    #pragma unroll
    for (int i = 0; i < 2; i++)
        #pragma unroll
        for (int j = 0; j < 4; j++)
            wmma::fill_fragment(acc[i][j], 0.0f);

    // prologue: fill STAGES-1 buffers
    #pragma unroll
    for (int s = 0; s < STAGES - 1; s++) {
        load_tile(s, s);
        cp_commit();
    }

    for (int kt = 0; kt < KT; kt++) {
        // issue load for kt+STAGES-1 (into buffer whose compute finished last iter)
        if (kt + STAGES - 1 < KT) load_tile((kt + STAGES - 1) % STAGES, kt + STAGES - 1);
        cp_commit();
        cp_wait<STAGES - 2>();
        __syncthreads();

        const float* As = sm + (kt % STAGES) * STAGE_FLOATS;
        const float* Bs = As + TM * AS_LD;

        #pragma unroll
        for (int kk = 0; kk < TK; kk += 8) {
            wmma::fragment<wmma::matrix_a, 16, 16, 8, wmma::precision::tf32, wmma::row_major> a[2];
            wmma::fragment<wmma::matrix_b, 16, 16, 8, wmma::precision::tf32, wmma::row_major> b[4];
            #pragma unroll
            for (int i = 0; i < 2; i++) {
                wmma::load_matrix_sync(a[i], As + (wm * 32 + i * 16) * AS_LD + kk, AS_LD);
                #pragma unroll
                for (int e = 0; e < a[i].num_elements; e++)
                    a[i].x[e] = wmma::__float_to_tf32(a[i].x[e]);
            }
            #pragma unroll
            for (int j = 0; j < 4; j++) {
                wmma::load_matrix_sync(b[j], Bs + kk * BS_LD + wn * 64 + j * 16, BS_LD);
                #pragma unroll
                for (int e = 0; e < b[j].num_elements; e++)
                    b[j].x[e] = wmma::__float_to_tf32(b[j].x[e]);
            }
            #pragma unroll
            for (int i = 0; i < 2; i++)
                #pragma unroll
                for (int j = 0; j < 4; j++)
                    wmma::mma_sync(acc[i][j], a[i], b[j], acc[i][j]);
        }
        __syncthreads();
    }

    #pragma unroll
    for (int i = 0; i < 2; i++)
        #pragma unroll
        for (int j = 0; j < 4; j++)
            wmma::store_matrix_sync(C + (size_t)(m0 + wm * 32 + i * 16) * N + n0 + wn * 64 + j * 16,
                                    acc[i][j], N, wmma::mem_row_major);
}

// ---------------- Flash attention: 256 threads, 8 warps (4 row x 2 col tiling) ----------------
#define BQ 64
#define SLD 68

#define ATTN_SMEM_FLOATS (6 * BQ * SLD + 3 * BQ)
#define ATTN_SMEM_BYTES  (ATTN_SMEM_FLOATS * 4)

__global__ void __launch_bounds__(256, 2) attn_kernel(
    const float* __restrict__ qkv, float* __restrict__ out)
{
    extern __shared__ float sm[];
    float* Qs = sm;
    float* Ks = Qs + BQ * SLD;
    float* Vs = Ks + BQ * SLD;
    float* Ss = Vs + BQ * SLD;
    float* Os = Ss + BQ * SLD;
    float* Ts = Os + BQ * SLD;
    float* mrow = Ts + BQ * SLD;
    float* lrow = mrow + BQ;
    float* arow = lrow + BQ;

    const int tid = threadIdx.x;
    const int wid = tid >> 5;
    const int lane = tid & 31;
    const int wr = wid >> 1;   // 0..3: 16-row group
    const int wc = wid & 1;    // 0..1: 32-col group
    const int qt = blockIdx.x;
    const int bh = blockIdx.y;
    const int b = bh >> 4;
    const int h = bh & 15;
    const float scale = 0.125f;

    // Load Q tile pre-scaled (64x64 -> 1024 float4 over 256 threads)
    #pragma unroll
    for (int f = tid; f < (BQ * DK) / 4; f += 256) {
        int r = f >> 4;
        int c4 = (f & 15) << 2;
        const float* p = qkv + (size_t)(b * SEQ + qt * BQ + r) * C3 + h * DK + c4;
        float4 v = *reinterpret_cast<const float4*>(p);
        v.x *= scale; v.y *= scale; v.z *= scale; v.w *= scale;
        *reinterpret_cast<float4*>(Qs + r * SLD + c4) = v;
    }
    for (int f = tid; f < BQ * SLD; f += 256) Os[f] = 0.0f;
    if (tid < BQ) { mrow[tid] = -INFINITY; lrow[tid] = 0.0f; }
    __syncthreads();

    for (int j = 0; j <= qt; j++) {
        const int jbase = j * BQ;

        // Load K and V tiles
        #pragma unroll
        for (int f = tid; f < (BQ * DK) / 4; f += 256) {
            int r = f >> 4;
            int c4 = (f & 15) << 2;
            size_t base = (size_t)(b * SEQ + jbase + r) * C3 + h * DK + c4;
            *reinterpret_cast<float4*>(Ks + r * SLD + c4) =
                *reinterpret_cast<const float4*>(qkv + base + CH);
            *reinterpret_cast<float4*>(Vs + r * SLD + c4) =
                *reinterpret_cast<const float4*>(qkv + base + 2 * CH);
        }
        __syncthreads();

        // S = Q * K^T  -- warp (wr,wc): rows [16wr,16wr+16), cols [32wc,32wc+32)
        {
            wmma::fragment<wmma::accumulator, 16, 16, 8, float> c[2];
            #pragma unroll
            for (int n = 0; n < 2; n++) wmma::fill_fragment(c[n], 0.0f);
            #pragma unroll
            for (int kk = 0; kk < DK; kk += 8) {
                wmma::fragment<wmma::matrix_a, 16, 16, 8, wmma::precision::tf32, wmma::row_major> a;
                wmma::load_matrix_sync(a, Qs + (wr * 16) * SLD + kk, SLD);
                #pragma unroll
                for (int e = 0; e < a.num_elements; e++) a.x[e] = wmma::__float_to_tf32(a.x[e]);
                #pragma unroll
                for (int n = 0; n < 2; n++) {
                    wmma::fragment<wmma::matrix_b, 16, 16, 8, wmma::precision::tf32, wmma::col_major> bf;
                    wmma::load_matrix_sync(bf, Ks + (wc * 32 + n * 16) * SLD + kk, SLD);
                    #pragma unroll
                    for (int e = 0; e < bf.num_elements; e++) bf.x[e] = wmma::__float_to_tf32(bf.x[e]);
                    wmma::mma_sync(c[n], a, bf, c[n]);
                }
            }
            #pragma unroll
            for (int n = 0; n < 2; n++)
                wmma::store_matrix_sync(Ss + (wr * 16) * SLD + wc * 32 + n * 16, c[n], SLD, wmma::mem_row_major);
        }
        __syncthreads();

        // Online softmax: warp wid owns rows [8*wid, 8*wid+8); lanes sweep 64 cols
        {
            #pragma unroll
            for (int rr = 0; rr < 8; rr++) {
                const int r = wid * 8 + rr;
                const int qglob = qt * BQ + r;
                int nvalid = qglob - jbase + 1;
                if (nvalid > BQ) nvalid = BQ;

                float v0 = (lane < nvalid) ? Ss[r * SLD + lane] : -INFINITY;
                float v1 = (lane + 32 < nvalid) ? Ss[r * SLD + lane + 32] : -INFINITY;
                float mx = fmaxf(v0, v1);
                #pragma unroll
                for (int o = 16; o > 0; o >>= 1)
                    mx = fmaxf(mx, __shfl_xor_sync(0xffffffff, mx, o));
                const float mo = mrow[r];
                mx = fmaxf(mx, mo);

                float p0 = (lane < nvalid) ? __expf(v0 - mx) : 0.0f;
                float p1 = (lane + 32 < nvalid) ? __expf(v1 - mx) : 0.0f;
                Ss[r * SLD + lane] = p0;
                Ss[r * SLD + lane + 32] = p1;
                float s = p0 + p1;
                #pragma unroll
                for (int o = 16; o > 0; o >>= 1)
                    s += __shfl_xor_sync(0xffffffff, s, o);

                if (lane == 0) {
                    const float al = __expf(mo - mx);
                    mrow[r] = mx;
                    lrow[r] = lrow[r] * al + s;
                    arow[r] = al;
                }
            }
        }
        __syncthreads();

        // Ts = P * V  -- warp (wr,wc): rows [16wr,+16), cols [32wc,+32)
        {
            wmma::fragment<wmma::accumulator, 16, 16, 8, float> c[2];
            #pragma unroll
            for (int n = 0; n < 2; n++) wmma::fill_fragment(c[n], 0.0f);
            #pragma unroll
            for (int kk = 0; kk < BQ; kk += 8) {
                wmma::fragment<wmma::matrix_a, 16, 16, 8, wmma::precision::tf32, wmma::row_major> a;
                wmma::load_matrix_sync(a, Ss + (wr * 16) * SLD + kk, SLD);
                #pragma unroll
                for (int e = 0; e < a.num_elements; e++) a.x[e] = wmma::__float_to_tf32(a.x[e]);
                #pragma unroll
                for (int n = 0; n < 2; n++) {
                    wmma::fragment<wmma::matrix_b, 16, 16, 8, wmma::precision::tf32, wmma::row_major> bf;
                    wmma::load_matrix_sync(bf, Vs + kk * SLD + wc * 32 + n * 16, SLD);
                    #pragma unroll
                    for (int e = 0; e < bf.num_elements; e++) bf.x[e] = wmma::__float_to_tf32(bf.x[e]);
                    wmma::mma_sync(c[n], a, bf, c[n]);
                }
            }
            #pragma unroll
            for (int n = 0; n < 2; n++)
                wmma::store_matrix_sync(Ts + (wr * 16) * SLD + wc * 32 + n * 16, c[n], SLD, wmma::mem_row_major);
        }
        __syncthreads();

        // O = O * alpha + Ts  (64*64/256 = 16 elems per thread)
        #pragma unroll
        for (int f = tid; f < BQ * DK; f += 256) {
            int r = f >> 6;
            int c = f & 63;
            Os[r * SLD + c] = Os[r * SLD + c] * arow[r] + Ts[r * SLD + c];
        }
        __syncthreads();
    }

    // out = O / l
    #pragma unroll
    for (int f = tid; f < BQ * DK; f += 256) {
        int r = f >> 6;
        int c = f & 63;
        out[(size_t)(b * SEQ + qt * BQ + r) * CH + h * DK + c] = Os[r * SLD + c] / lrow[r];
    }
}

// ---------------- launch ----------------
extern "C" void kernel_launch(void* const* d_in, const int* in_sizes, int n_in,
                              void* d_out, int out_size)
{
    const float* x     = (const float*)d_in[0];
    const float* w_qkv = (const float*)d_in[1];
    const float* w_out = (const float*)d_in[2];
    float* out = (float*)d_out;

    float* qkv = nullptr;
    float* att = nullptr;
    cudaGetSymbolAddress((void**)&qkv, g_qkv);
    cudaGetSymbolAddress((void**)&att, g_attn);

    static bool configured = false;
    if (!configured) {
        cudaFuncSetAttribute(gemm_tf32_kernel, cudaFuncAttributeMaxDynamicSharedMemorySize, GEMM_SMEM_BYTES);
        cudaFuncSetAttribute(attn_kernel, cudaFuncAttributeMaxDynamicSharedMemorySize, ATTN_SMEM_BYTES);
        configured = true;
    }

    // 1) qkv = x @ w_qkv   [8192 x 3072]
    {
        dim3 grid(C3 / TN, ROWS / TM);
        gemm_tf32_kernel<<<grid, 256, GEMM_SMEM_BYTES>>>(x, w_qkv, qkv, ROWS, C3, CH);
    }
    // 2) flash attention
    {
        dim3 grid(SEQ / BQ, BATCH * NHEAD);
        attn_kernel<<<grid, 256, ATTN_SMEM_BYTES>>>(qkv, att);
    }
    // 3) out = attn @ w_out  [8192 x 1024]
    {
        dim3 grid(CH / TN, ROWS / TM);
        gemm_tf32_kernel<<<grid, 256, GEMM_SMEM_BYTES>>>(att, w_out, out, ROWS, CH, CH);
    }
}

// round 3
// speedup vs baseline: 1.7314x; 1.6197x over previous
#include <cuda_runtime.h>
#include <cuda_bf16.h>
#include <mma.h>
#include <math.h>
#include <stdint.h>

using namespace nvcuda;

#define BATCH 4
#define SEQ   2048
#define CH    1024
#define NHEAD 16
#define DK    64
#define C3    3072
#define ROWS  (BATCH*SEQ)   // 8192

// ---------------- scratch ----------------
__device__ float g_qkv[(size_t)ROWS * C3];    // 96 MB
__device__ float g_attn[(size_t)ROWS * CH];   // 32 MB (tf32-rounded attention out)
__device__ float g_xr[(size_t)ROWS * CH];     // 32 MB (x rounded)
__device__ float g_wqkvr[(size_t)CH * C3];    // 12 MB
__device__ float g_woutr[(size_t)CH * CH];    // 4 MB

// ---------------- helpers ----------------
__device__ __forceinline__ void cp_async16(void* smem_dst, const void* gmem_src) {
    unsigned s = (unsigned)__cvta_generic_to_shared(smem_dst);
    asm volatile("cp.async.cg.shared.global [%0], [%1], 16;\n" :: "r"(s), "l"(gmem_src));
}
__device__ __forceinline__ void cp_commit() {
    asm volatile("cp.async.commit_group;\n" ::);
}
template<int N>
__device__ __forceinline__ void cp_wait() {
    asm volatile("cp.async.wait_group %0;\n" :: "n"(N));
}
__device__ __forceinline__ uint32_t cvt_tf32(float x) {
    uint32_t u;
    asm("cvt.rna.tf32.f32 %0, %1;" : "=r"(u) : "f"(x));
    return u;
}
__device__ __forceinline__ float f2tf32f(float x) {
    return __uint_as_float(cvt_tf32(x));
}
__device__ __forceinline__ void mma_tf32(float c[4], const uint32_t a[4], uint32_t b0, uint32_t b1) {
    asm volatile(
        "mma.sync.aligned.m16n8k8.row.col.f32.tf32.tf32.f32 "
        "{%0,%1,%2,%3}, {%4,%5,%6,%7}, {%8,%9}, {%0,%1,%2,%3};"
        : "+f"(c[0]), "+f"(c[1]), "+f"(c[2]), "+f"(c[3])
        : "r"(a[0]), "r"(a[1]), "r"(a[2]), "r"(a[3]), "r"(b0), "r"(b1));
}

// ---------------- tf32 pre-round pass ----------------
__global__ void round_tf32_kernel(const float4* __restrict__ in, float4* __restrict__ out, int n4) {
    int i = blockIdx.x * blockDim.x + threadIdx.x;
    int stride = gridDim.x * blockDim.x;
    for (; i < n4; i += stride) {
        float4 v = in[i];
        v.x = f2tf32f(v.x); v.y = f2tf32f(v.y); v.z = f2tf32f(v.z); v.w = f2tf32f(v.w);
        out[i] = v;
    }
}

// ---------------- TF32 wmma GEMM (inputs pre-rounded, no per-fragment cvt) ----------------
#define TM 128
#define TN 128
#define TK 16
#define AS_LD 20
#define BS_LD 132
#define STAGES 4
#define STAGE_FLOATS (TM*AS_LD + TK*BS_LD)   // 4672
#define GEMM_SMEM_BYTES (STAGES * STAGE_FLOATS * 4)

__global__ void __launch_bounds__(256, 2) gemm_tf32_kernel(
    const float* __restrict__ A, const float* __restrict__ B,
    float* __restrict__ C, int M, int N, int K)
{
    extern __shared__ float sm[];

    const int tid = threadIdx.x;
    const int m0 = blockIdx.y * TM;
    const int n0 = blockIdx.x * TN;
    const int wid = tid >> 5;
    const int wm = wid & 3;
    const int wn = wid >> 2;
    const int KT = K / TK;

    const int ar0 = tid >> 2, ac0 = (tid & 3) << 2;
    const int ar1 = (tid + 256) >> 2, ac1 = ac0;
    const int br0 = tid >> 5, bc0 = (tid & 31) << 2;
    const int br1 = (tid + 256) >> 5, bc1 = bc0;

    auto load_tile = [&](int buf, int kt) {
        float* As = sm + buf * STAGE_FLOATS;
        float* Bs = As + TM * AS_LD;
        const int k0 = kt * TK;
        cp_async16(As + ar0 * AS_LD + ac0, A + (size_t)(m0 + ar0) * K + k0 + ac0);
        cp_async16(As + ar1 * AS_LD + ac1, A + (size_t)(m0 + ar1) * K + k0 + ac1);
        cp_async16(Bs + br0 * BS_LD + bc0, B + (size_t)(k0 + br0) * N + n0 + bc0);
        cp_async16(Bs + br1 * BS_LD + bc1, B + (size_t)(k0 + br1) * N + n0 + bc1);
    };

    wmma::fragment<wmma::accumulator, 16, 16, 8, float> acc[2][4];
    #pragma unroll
    for (int i = 0; i < 2; i++)
        #pragma unroll
        for (int j = 0; j < 4; j++)
            wmma::fill_fragment(acc[i][j], 0.0f);

    #pragma unroll
    for (int s = 0; s < STAGES - 1; s++) {
        load_tile(s, s);
        cp_commit();
    }

    for (int kt = 0; kt < KT; kt++) {
        if (kt + STAGES - 1 < KT) load_tile((kt + STAGES - 1) % STAGES, kt + STAGES - 1);
        cp_commit();
        cp_wait<STAGES - 2>();
        __syncthreads();

        const float* As = sm + (kt % STAGES) * STAGE_FLOATS;
        const float* Bs = As + TM * AS_LD;

        #pragma unroll
        for (int kk = 0; kk < TK; kk += 8) {
            wmma::fragment<wmma::matrix_a, 16, 16, 8, wmma::precision::tf32, wmma::row_major> a[2];
            wmma::fragment<wmma::matrix_b, 16, 16, 8, wmma::precision::tf32, wmma::row_major> b[4];
            #pragma unroll
            for (int i = 0; i < 2; i++)
                wmma::load_matrix_sync(a[i], As + (wm * 32 + i * 16) * AS_LD + kk, AS_LD);
            #pragma unroll
            for (int j = 0; j < 4; j++)
                wmma::load_matrix_sync(b[j], Bs + kk * BS_LD + wn * 64 + j * 16, BS_LD);
            #pragma unroll
            for (int i = 0; i < 2; i++)
                #pragma unroll
                for (int j = 0; j < 4; j++)
                    wmma::mma_sync(acc[i][j], a[i], b[j], acc[i][j]);
        }
        __syncthreads();
    }

    #pragma unroll
    for (int i = 0; i < 2; i++)
        #pragma unroll
        for (int j = 0; j < 4; j++)
            wmma::store_matrix_sync(C + (size_t)(m0 + wm * 32 + i * 16) * N + n0 + wn * 64 + j * 16,
                                    acc[i][j], N, wmma::mem_row_major);
}

// ---------------- Flash attention v3: FA2-style, PTX mma, registers ----------------
// 4 warps, 64 q-rows/block (16 per warp), 64-key tiles, double-buffered cp.async K/V.
#define AT_SLD 68
#define AT_BUF (2 * 64 * AT_SLD)          // K+V floats per buffer = 8704
#define AT_SMEM_FLOATS (2 * AT_BUF)       // 17408
#define AT_SMEM_BYTES (AT_SMEM_FLOATS * 4)  // 69632

__global__ void __launch_bounds__(128, 3) attn_kernel(
    const float* __restrict__ qkv, float* __restrict__ out)
{
    extern __shared__ float sm[];
    const int tid = threadIdx.x;
    const int lane = tid & 31;
    const int w = tid >> 5;
    const int g = lane >> 2;       // groupID (row within 8)
    const int tig = lane & 3;      // thread-in-group
    const int qt = blockIdx.x;
    const int bh = blockIdx.y;
    const int b = bh >> 4;
    const int h = bh & 15;

    // ---- K/V tile fill via cp.async (raw fp32; consumers convert) ----
    auto fill = [&](int buf, int j) {
        float* K = sm + buf * AT_BUF;
        float* V = K + 64 * AT_SLD;
        const float* gb = qkv + (size_t)(b * SEQ + j * 64) * C3 + h * DK;
        #pragma unroll
        for (int i = 0; i < 8; i++) {
            int f = tid + i * 128;
            int r = f >> 4, c4 = (f & 15) << 2;
            const float* src = gb + (size_t)r * C3 + c4;
            cp_async16(K + r * AT_SLD + c4, src + CH);
            cp_async16(V + r * AT_SLD + c4, src + 2 * CH);
        }
    };

    fill(0, 0);
    cp_commit();

    // ---- Q tile: scaled + tf32-rounded into buf1's K region (alias, consumed before j=1 prefetch) ----
    float* Qs = sm + AT_BUF;
    {
        const float* gq = qkv + (size_t)(b * SEQ + qt * 64) * C3 + h * DK;
        #pragma unroll
        for (int f = tid; f < 1024; f += 128) {
            int r = f >> 4, c4 = (f & 15) << 2;
            float4 v = *reinterpret_cast<const float4*>(gq + (size_t)r * C3 + c4);
            v.x = f2tf32f(v.x * 0.125f);
            v.y = f2tf32f(v.y * 0.125f);
            v.z = f2tf32f(v.z * 0.125f);
            v.w = f2tf32f(v.w * 0.125f);
            *reinterpret_cast<float4*>(Qs + r * AT_SLD + c4) = v;
        }
    }
    __syncthreads();

    // ---- Q a-fragments (m16n8k8 tf32 A layout): 8 k-chunks x 4 regs ----
    uint32_t aq[8][4];
    {
        const float* qb = Qs + (w * 16 + g) * AT_SLD + tig;
        #pragma unroll
        for (int kk = 0; kk < 8; kk++) {
            aq[kk][0] = __float_as_uint(qb[kk * 8]);
            aq[kk][1] = __float_as_uint(qb[kk * 8 + 8 * AT_SLD]);
            aq[kk][2] = __float_as_uint(qb[kk * 8 + 4]);
            aq[kk][3] = __float_as_uint(qb[kk * 8 + 8 * AT_SLD + 4]);
        }
    }
    __syncthreads();   // all warps done with Qs before buf1 prefetch

    float oc[8][4];
    #pragma unroll
    for (int t = 0; t < 8; t++)
        #pragma unroll
        for (int e = 0; e < 4; e++) oc[t][e] = 0.0f;
    float mA = -INFINITY, mB = -INFINITY, lA = 0.0f, lB = 0.0f;

    const int koff = g * AT_SLD + tig;    // K b-frag: (row=g)*ld + (col=tig)
    const int voff = tig * AT_SLD + g;    // V b-frag: (row=tig)*ld + (col=g)
    const int rlocA = w * 16 + g;

    for (int j = 0; j <= qt; j++) {
        cp_wait<0>();
        __syncthreads();
        if (j < qt) { fill((j + 1) & 1, j + 1); cp_commit(); }

        const float* K = sm + (j & 1) * AT_BUF;
        const float* V = K + 64 * AT_SLD;

        // ---- S = Q * K^T : 8 n-tiles x 8 k-chunks ----
        float sc[8][4];
        #pragma unroll
        for (int t = 0; t < 8; t++)
            #pragma unroll
            for (int e = 0; e < 4; e++) sc[t][e] = 0.0f;

        #pragma unroll
        for (int kk = 0; kk < 8; kk++) {
            #pragma unroll
            for (int t = 0; t < 8; t++) {
                const float* kp = K + t * 8 * AT_SLD + kk * 8 + koff;
                uint32_t b0 = cvt_tf32(kp[0]);
                uint32_t b1 = cvt_tf32(kp[4]);
                mma_tf32(sc[t], aq[kk], b0, b1);
            }
        }

        // ---- causal mask on diagonal tile ----
        if (j == qt) {
            #pragma unroll
            for (int t = 0; t < 8; t++) {
                int c0 = t * 8 + 2 * tig;
                int c1 = c0 + 1;
                if (c0 > rlocA)     sc[t][0] = -INFINITY;
                if (c1 > rlocA)     sc[t][1] = -INFINITY;
                if (c0 > rlocA + 8) sc[t][2] = -INFINITY;
                if (c1 > rlocA + 8) sc[t][3] = -INFINITY;
            }
        }

        // ---- online softmax (registers + quad shuffles) ----
        float mxA = -INFINITY, mxB = -INFINITY;
        #pragma unroll
        for (int t = 0; t < 8; t++) {
            mxA = fmaxf(mxA, fmaxf(sc[t][0], sc[t][1]));
            mxB = fmaxf(mxB, fmaxf(sc[t][2], sc[t][3]));
        }
        #pragma unroll
        for (int o = 1; o <= 2; o <<= 1) {
            mxA = fmaxf(mxA, __shfl_xor_sync(0xffffffffu, mxA, o));
            mxB = fmaxf(mxB, __shfl_xor_sync(0xffffffffu, mxB, o));
        }
        const float mA2 = fmaxf(mA, mxA);
        const float mB2 = fmaxf(mB, mxB);
        const float alA = __expf(mA - mA2);
        const float alB = __expf(mB - mB2);

        float sA = 0.0f, sB = 0.0f;
        #pragma unroll
        for (int t = 0; t < 8; t++) {
            sc[t][0] = __expf(sc[t][0] - mA2);
            sc[t][1] = __expf(sc[t][1] - mA2);
            sc[t][2] = __expf(sc[t][2] - mB2);
            sc[t][3] = __expf(sc[t][3] - mB2);
            sA += sc[t][0] + sc[t][1];
            sB += sc[t][2] + sc[t][3];
        }
        #pragma unroll
        for (int o = 1; o <= 2; o <<= 1) {
            sA += __shfl_xor_sync(0xffffffffu, sA, o);
            sB += __shfl_xor_sync(0xffffffffu, sB, o);
        }
        mA = mA2; mB = mB2;
        lA = lA * alA + sA;
        lB = lB * alB + sB;

        #pragma unroll
        for (int t = 0; t < 8; t++) {
            oc[t][0] *= alA; oc[t][1] *= alA;
            oc[t][2] *= alB; oc[t][3] *= alB;
        }

        // ---- O += P * V : remap P (C-layout -> A-layout via quad shuffles) ----
        #pragma unroll
        for (int t = 0; t < 8; t++) {
            const int src0 = (lane & ~3) | (tig >> 1);
            const int src1 = src0 + 2;
            float y00 = __shfl_sync(0xffffffffu, sc[t][0], src0);
            float y01 = __shfl_sync(0xffffffffu, sc[t][1], src0);
            float y10 = __shfl_sync(0xffffffffu, sc[t][2], src0);
            float y11 = __shfl_sync(0xffffffffu, sc[t][3], src0);
            float z00 = __shfl_sync(0xffffffffu, sc[t][0], src1);
            float z01 = __shfl_sync(0xffffffffu, sc[t][1], src1);
            float z10 = __shfl_sync(0xffffffffu, sc[t][2], src1);
            float z11 = __shfl_sync(0xffffffffu, sc[t][3], src1);
            const bool odd = (tig & 1);
            uint32_t ap[4];
            ap[0] = cvt_tf32(odd ? y01 : y00);
            ap[1] = cvt_tf32(odd ? y11 : y10);
            ap[2] = cvt_tf32(odd ? z01 : z00);
            ap[3] = cvt_tf32(odd ? z11 : z10);

            const float* vp = V + t * 8 * AT_SLD + voff;
            #pragma unroll
            for (int tn = 0; tn < 8; tn++) {
                uint32_t b0 = cvt_tf32(vp[tn * 8]);
                uint32_t b1 = cvt_tf32(vp[tn * 8 + 4 * AT_SLD]);
                mma_tf32(oc[tn], ap, b0, b1);
            }
        }
    }

    // ---- epilogue: out = O / l, tf32-rounded (GEMM2 reads it cvt-free) ----
    const float iA = 1.0f / lA;
    const float iB = 1.0f / lB;
    float* ob = out + (size_t)(b * SEQ + qt * 64 + w * 16 + g) * CH + h * DK + 2 * tig;
    #pragma unroll
    for (int t = 0; t < 8; t++) {
        float2 vA, vB;
        vA.x = f2tf32f(oc[t][0] * iA);
        vA.y = f2tf32f(oc[t][1] * iA);
        vB.x = f2tf32f(oc[t][2] * iB);
        vB.y = f2tf32f(oc[t][3] * iB);
        *reinterpret_cast<float2*>(ob + t * 8) = vA;
        *reinterpret_cast<float2*>(ob + 8 * CH + t * 8) = vB;
    }
}

// ---------------- launch ----------------
extern "C" void kernel_launch(void* const* d_in, const int* in_sizes, int n_in,
                              void* d_out, int out_size)
{
    const float* x     = (const float*)d_in[0];
    const float* w_qkv = (const float*)d_in[1];
    const float* w_out = (const float*)d_in[2];
    float* out = (float*)d_out;

    float *qkv, *att, *xr, *wqkvr, *woutr;
    cudaGetSymbolAddress((void**)&qkv,   g_qkv);
    cudaGetSymbolAddress((void**)&att,   g_attn);
    cudaGetSymbolAddress((void**)&xr,    g_xr);
    cudaGetSymbolAddress((void**)&wqkvr, g_wqkvr);
    cudaGetSymbolAddress((void**)&woutr, g_woutr);

    cudaFuncSetAttribute(gemm_tf32_kernel, cudaFuncAttributeMaxDynamicSharedMemorySize, GEMM_SMEM_BYTES);
    cudaFuncSetAttribute(attn_kernel, cudaFuncAttributeMaxDynamicSharedMemorySize, AT_SMEM_BYTES);

    // 0) pre-round inputs to tf32 (RN) once
    round_tf32_kernel<<<512, 256>>>((const float4*)x,     (float4*)xr,    (ROWS * CH) / 4);
    round_tf32_kernel<<<256, 256>>>((const float4*)w_qkv, (float4*)wqkvr, (CH * C3) / 4);
    round_tf32_kernel<<<128, 256>>>((const float4*)w_out, (float4*)woutr, (CH * CH) / 4);

    // 1) qkv = x @ w_qkv   [8192 x 3072]
    {
        dim3 grid(C3 / TN, ROWS / TM);
        gemm_tf32_kernel<<<grid, 256, GEMM_SMEM_BYTES>>>(xr, wqkvr, qkv, ROWS, C3, CH);
    }
    // 2) flash attention (writes tf32-rounded output)
    {
        dim3 grid(SEQ / 64, BATCH * NHEAD);
        attn_kernel<<<grid, 128, AT_SMEM_BYTES>>>(qkv, att);
    }
    // 3) out = attn @ w_out  [8192 x 1024]
    {
        dim3 grid(CH / TN, ROWS / TM);
        gemm_tf32_kernel<<<grid, 256, GEMM_SMEM_BYTES>>>(att, woutr, out, ROWS, CH, CH);
    }
}

// round 5
// speedup vs baseline: 5.0220x; 2.9005x over previous
#include <cuda_runtime.h>
#include <cuda_fp16.h>
#include <math.h>
#include <stdint.h>

#define BATCH 4
#define SEQ   2048
#define CH    1024
#define NHEAD 16
#define DK    64
#define C3    3072
#define ROWS  (BATCH*SEQ)   // 8192

// ---------------- scratch ----------------
__device__ __align__(16) __half g_qkvh[(size_t)ROWS * C3];   // 48 MB (GEMM1 out, fp16)
__device__ __align__(16) __half g_attnh[(size_t)ROWS * CH];  // 16 MB (attention out, fp16)
__device__ __align__(16) __half g_xh[(size_t)ROWS * CH];     // 16 MB (x, fp16)
__device__ __align__(16) __half g_wqkvT[(size_t)C3 * CH];    // 6 MB ([3072,1024] = [N,K])
__device__ __align__(16) __half g_woutT[(size_t)CH * CH];    // 2 MB
__device__ __align__(16) __half g_vT[(size_t)BATCH * NHEAD * DK * SEQ]; // 16 MB [bh][d][t]

// ---------------- helpers ----------------
__device__ __forceinline__ void cp_async16(void* smem_dst, const void* gmem_src) {
    unsigned s = (unsigned)__cvta_generic_to_shared(smem_dst);
    asm volatile("cp.async.cg.shared.global [%0], [%1], 16;\n" :: "r"(s), "l"(gmem_src));
}
__device__ __forceinline__ void cp_commit() {
    asm volatile("cp.async.commit_group;\n" ::);
}
template<int N>
__device__ __forceinline__ void cp_wait() {
    asm volatile("cp.async.wait_group %0;\n" :: "n"(N));
}
__device__ __forceinline__ void mma_f16(float c[4], const uint32_t a[4], uint32_t b0, uint32_t b1) {
    asm volatile(
        "mma.sync.aligned.m16n8k16.row.col.f32.f16.f16.f32 "
        "{%0,%1,%2,%3}, {%4,%5,%6,%7}, {%8,%9}, {%0,%1,%2,%3};"
        : "+f"(c[0]), "+f"(c[1]), "+f"(c[2]), "+f"(c[3])
        : "r"(a[0]), "r"(a[1]), "r"(a[2]), "r"(a[3]), "r"(b0), "r"(b1));
}
__device__ __forceinline__ uint32_t pack_h2(float x, float y) {
    __half2 h = __floats2half2_rn(x, y);
    return *reinterpret_cast<uint32_t*>(&h);
}

// ---------------- pre-pass kernels ----------------
__global__ void f2h_kernel(const float4* __restrict__ in, __half2* __restrict__ out, int n4) {
    int i = blockIdx.x * blockDim.x + threadIdx.x;
    int stride = gridDim.x * blockDim.x;
    for (; i < n4; i += stride) {
        float4 v = in[i];
        out[2 * i]     = __floats2half2_rn(v.x, v.y);
        out[2 * i + 1] = __floats2half2_rn(v.z, v.w);
    }
}

// out[c][r] = half(in[r][c]); in: [R][C] float
__global__ void wtrans_kernel(const float* __restrict__ in, __half* __restrict__ out,
                              int R, int C) {
    __shared__ float t[32][33];
    int bx = blockIdx.x * 32;   // col tile
    int by = blockIdx.y * 32;   // row tile
    #pragma unroll
    for (int j = 0; j < 32; j += 8)
        t[threadIdx.y + j][threadIdx.x] = in[(size_t)(by + threadIdx.y + j) * C + bx + threadIdx.x];
    __syncthreads();
    #pragma unroll
    for (int j = 0; j < 32; j += 8)
        out[(size_t)(bx + threadIdx.y + j) * R + by + threadIdx.x] =
            __float2half(t[threadIdx.x][threadIdx.y + j]);
}

// vT[bh][d][t] = qkvh[b*SEQ+t][2*CH + h*64 + d]
__global__ void vtrans_kernel(const __half* __restrict__ qkvh, __half* __restrict__ vT) {
    __shared__ __half s[32][34];
    const int bh = blockIdx.z;
    const int b = bh >> 4, h = bh & 15;
    const int t0 = blockIdx.x * 32;
    const int d0 = blockIdx.y * 32;
    #pragma unroll
    for (int j = 0; j < 32; j += 8)
        s[threadIdx.y + j][threadIdx.x] =
            qkvh[(size_t)(b * SEQ + t0 + threadIdx.y + j) * C3 + 2 * CH + h * 64 + d0 + threadIdx.x];
    __syncthreads();
    #pragma unroll
    for (int j = 0; j < 32; j += 8)
        vT[((size_t)bh * 64 + d0 + threadIdx.y + j) * SEQ + t0 + threadIdx.x] =
            s[threadIdx.x][threadIdx.y + j];
}

// ---------------- fp16 GEMM: C[M,N] = A[M,K] @ Bt[N,K]^T, fp32 accum ----------------
#define GTM 128
#define GTN 128
#define GTK 32
#define GLD 40                      // padded row stride (halves)
#define G_ASTG (128 * GLD)          // 5120 halves per operand per stage
#define G_STG  (2 * G_ASTG)         // 10240
#define GSTAGES 4
#define GEMM_SMEM (GSTAGES * G_STG * 2)   // 81920 bytes

template<bool HALF_OUT>
__global__ void __launch_bounds__(256, 2) gemm_f16_kernel(
    const __half* __restrict__ A, const __half* __restrict__ Bt,
    void* __restrict__ Cout, int Ntot, int K)
{
    extern __shared__ __half sh[];
    const int tid = threadIdx.x;
    const int lane = tid & 31;
    const int wid = tid >> 5;
    const int wm = wid & 3;      // 4 warps -> 32-row strips
    const int wn = wid >> 2;     // 2 warps -> 64-col strips
    const int m0 = blockIdx.y * GTM;
    const int n0 = blockIdx.x * GTN;
    const int KT = K / GTK;
    const int g = lane >> 2;
    const int c2 = 2 * (lane & 3);

    auto fill = [&](int buf, int s) {
        __half* As = sh + buf * G_STG;
        __half* Bs = As + G_ASTG;
        const int k0 = s * GTK;
        #pragma unroll
        for (int j = 0; j < 2; j++) {
            int c = tid + j * 256;
            int row = c >> 2, ch = (c & 3) << 3;
            cp_async16(As + row * GLD + ch, A + (size_t)(m0 + row) * K + k0 + ch);
        }
        #pragma unroll
        for (int j = 0; j < 2; j++) {
            int c = tid + j * 256;
            int row = c >> 2, ch = (c & 3) << 3;
            cp_async16(Bs + row * GLD + ch, Bt + (size_t)(n0 + row) * K + k0 + ch);
        }
    };

    float acc[2][8][4];
    #pragma unroll
    for (int i = 0; i < 2; i++)
        #pragma unroll
        for (int j = 0; j < 8; j++)
            #pragma unroll
            for (int e = 0; e < 4; e++) acc[i][j][e] = 0.0f;

    fill(0, 0); cp_commit();
    fill(1, 1); cp_commit();
    fill(2, 2); cp_commit();

    for (int s = 0; s < KT; s++) {
        if (s + 3 < KT) fill((s + 3) & 3, s + 3);
        cp_commit();
        cp_wait<2>();
        __syncthreads();

        const __half* As = sh + (s & 3) * G_STG;
        const __half* Bs = As + G_ASTG;

        #pragma unroll
        for (int kk = 0; kk < 2; kk++) {
            uint32_t a[2][4];
            #pragma unroll
            for (int mt = 0; mt < 2; mt++) {
                const __half* p = As + (wm * 32 + mt * 16 + g) * GLD + kk * 16 + c2;
                a[mt][0] = *reinterpret_cast<const uint32_t*>(p);
                a[mt][1] = *reinterpret_cast<const uint32_t*>(p + 8 * GLD);
                a[mt][2] = *reinterpret_cast<const uint32_t*>(p + 8);
                a[mt][3] = *reinterpret_cast<const uint32_t*>(p + 8 * GLD + 8);
            }
            #pragma unroll
            for (int nt = 0; nt < 8; nt++) {
                const __half* q = Bs + (wn * 64 + nt * 8 + g) * GLD + kk * 16 + c2;
                uint32_t b0 = *reinterpret_cast<const uint32_t*>(q);
                uint32_t b1 = *reinterpret_cast<const uint32_t*>(q + 8);
                mma_f16(acc[0][nt], a[0], b0, b1);
                mma_f16(acc[1][nt], a[1], b0, b1);
            }
        }
        __syncthreads();
    }

    // epilogue
    #pragma unroll
    for (int mt = 0; mt < 2; mt++) {
        #pragma unroll
        for (int nt = 0; nt < 8; nt++) {
            const int row = m0 + wm * 32 + mt * 16 + g;
            const int col = n0 + wn * 64 + nt * 8 + c2;
            if (HALF_OUT) {
                __half* Ch = (__half*)Cout;
                __half2 v0 = __floats2half2_rn(acc[mt][nt][0], acc[mt][nt][1]);
                __half2 v1 = __floats2half2_rn(acc[mt][nt][2], acc[mt][nt][3]);
                *reinterpret_cast<__half2*>(Ch + (size_t)row * Ntot + col) = v0;
                *reinterpret_cast<__half2*>(Ch + (size_t)(row + 8) * Ntot + col) = v1;
            } else {
                float* Cf = (float*)Cout;
                *reinterpret_cast<float2*>(Cf + (size_t)row * Ntot + col) =
                    make_float2(acc[mt][nt][0], acc[mt][nt][1]);
                *reinterpret_cast<float2*>(Cf + (size_t)(row + 8) * Ntot + col) =
                    make_float2(acc[mt][nt][2], acc[mt][nt][3]);
            }
        }
    }
}

// ---------------- Flash attention, fp16 mma ----------------
// 4 warps, 64 q rows (16/warp), 64-key j-tiles, double-buffered K/V, V pre-transposed.
#define AT_LD 72                               // padded stride (halves)
#define AT_TILE (64 * AT_LD)                   // 4608 halves per tile
#define AT_BUF (2 * AT_TILE)                   // K+V per buffer
#define AT_SMEM_HALVES (2 * AT_BUF + AT_TILE)  // 2 bufs + Q
#define AT_SMEM_BYTES (AT_SMEM_HALVES * 2)     // 46080

__global__ void __launch_bounds__(128, 3) attn_kernel(
    const __half* __restrict__ qkvh, const __half* __restrict__ vT,
    __half* __restrict__ out)
{
    extern __shared__ __half smh[];
    const int tid = threadIdx.x;
    const int lane = tid & 31;
    const int w = tid >> 5;
    const int g = lane >> 2;
    const int tig = lane & 3;
    const int c2 = 2 * tig;
    const int qt = blockIdx.x;
    const int bh = blockIdx.y;
    const int b = bh >> 4;
    const int h = bh & 15;

    __half* Qs = smh + 2 * AT_BUF;

    auto fill = [&](int buf, int j) {
        __half* K = smh + buf * AT_BUF;
        __half* V = K + AT_TILE;
        const __half* kg = qkvh + (size_t)(b * SEQ + j * 64) * C3 + CH + h * 64;
        const __half* vg = vT + ((size_t)bh * 64) * SEQ + j * 64;
        #pragma unroll
        for (int i = 0; i < 4; i++) {
            int f = tid + i * 128;
            int r = f >> 3, ch = (f & 7) << 3;
            cp_async16(K + r * AT_LD + ch, kg + (size_t)r * C3 + ch);
            cp_async16(V + r * AT_LD + ch, vg + (size_t)r * SEQ + ch);
        }
    };

    fill(0, 0);
    cp_commit();

    // Q tile -> smem (plain loads), then per-warp a-fragments, scaled by 1/8 (exact)
    {
        const __half* gq = qkvh + (size_t)(b * SEQ + qt * 64) * C3 + h * 64;
        #pragma unroll
        for (int f = tid; f < 512; f += 128) {
            int r = f >> 3, ch = (f & 7) << 3;
            *reinterpret_cast<uint4*>(Qs + r * AT_LD + ch) =
                *reinterpret_cast<const uint4*>(gq + (size_t)r * C3 + ch);
        }
    }
    __syncthreads();

    uint32_t aq[4][4];
    {
        const __half2 sc8 = __float2half2_rn(0.125f);
        const __half* p = Qs + (w * 16 + g) * AT_LD + c2;
        #pragma unroll
        for (int kk = 0; kk < 4; kk++) {
            __half2 v0 = *reinterpret_cast<const __half2*>(p + kk * 16);
            __half2 v1 = *reinterpret_cast<const __half2*>(p + kk * 16 + 8 * AT_LD);
            __half2 v2 = *reinterpret_cast<const __half2*>(p + kk * 16 + 8);
            __half2 v3 = *reinterpret_cast<const __half2*>(p + kk * 16 + 8 * AT_LD + 8);
            v0 = __hmul2(v0, sc8); v1 = __hmul2(v1, sc8);
            v2 = __hmul2(v2, sc8); v3 = __hmul2(v3, sc8);
            aq[kk][0] = *reinterpret_cast<uint32_t*>(&v0);
            aq[kk][1] = *reinterpret_cast<uint32_t*>(&v1);
            aq[kk][2] = *reinterpret_cast<uint32_t*>(&v2);
            aq[kk][3] = *reinterpret_cast<uint32_t*>(&v3);
        }
    }

    float oc[8][4];
    #pragma unroll
    for (int t = 0; t < 8; t++)
        #pragma unroll
        for (int e = 0; e < 4; e++) oc[t][e] = 0.0f;
    float mA = -INFINITY, mB = -INFINITY, lA = 0.0f, lB = 0.0f;
    const int rlocA = w * 16 + g;

    for (int j = 0; j <= qt; j++) {
        cp_wait<0>();
        __syncthreads();
        if (j < qt) { fill((j + 1) & 1, j + 1); cp_commit(); }

        const __half* K = smh + (j & 1) * AT_BUF;
        const __half* V = K + AT_TILE;

        // ---- S = Q*K^T : 8 n-tiles x 4 k16-steps ----
        float sc[8][4];
        #pragma unroll
        for (int t = 0; t < 8; t++)
            #pragma unroll
            for (int e = 0; e < 4; e++) sc[t][e] = 0.0f;

        #pragma unroll
        for (int kk = 0; kk < 4; kk++) {
            #pragma unroll
            for (int nt = 0; nt < 8; nt++) {
                const __half* kp = K + (nt * 8 + g) * AT_LD + kk * 16 + c2;
                uint32_t b0 = *reinterpret_cast<const uint32_t*>(kp);
                uint32_t b1 = *reinterpret_cast<const uint32_t*>(kp + 8);
                mma_f16(sc[nt], aq[kk], b0, b1);
            }
        }

        // ---- causal mask on diagonal tile ----
        if (j == qt) {
            #pragma unroll
            for (int t = 0; t < 8; t++) {
                int cc0 = t * 8 + c2;
                int cc1 = cc0 + 1;
                if (cc0 > rlocA)     sc[t][0] = -INFINITY;
                if (cc1 > rlocA)     sc[t][1] = -INFINITY;
                if (cc0 > rlocA + 8) sc[t][2] = -INFINITY;
                if (cc1 > rlocA + 8) sc[t][3] = -INFINITY;
            }
        }

        // ---- online softmax ----
        float mxA = -INFINITY, mxB = -INFINITY;
        #pragma unroll
        for (int t = 0; t < 8; t++) {
            mxA = fmaxf(mxA, fmaxf(sc[t][0], sc[t][1]));
            mxB = fmaxf(mxB, fmaxf(sc[t][2], sc[t][3]));
        }
        #pragma unroll
        for (int o = 1; o <= 2; o <<= 1) {
            mxA = fmaxf(mxA, __shfl_xor_sync(0xffffffffu, mxA, o));
            mxB = fmaxf(mxB, __shfl_xor_sync(0xffffffffu, mxB, o));
        }
        const float mA2 = fmaxf(mA, mxA);
        const float mB2 = fmaxf(mB, mxB);
        const float alA = __expf(mA - mA2);
        const float alB = __expf(mB - mB2);

        float sA = 0.0f, sB = 0.0f;
        #pragma unroll
        for (int t = 0; t < 8; t++) {
            sc[t][0] = __expf(sc[t][0] - mA2);
            sc[t][1] = __expf(sc[t][1] - mA2);
            sc[t][2] = __expf(sc[t][2] - mB2);
            sc[t][3] = __expf(sc[t][3] - mB2);
            sA += sc[t][0] + sc[t][1];
            sB += sc[t][2] + sc[t][3];
        }
        #pragma unroll
        for (int o = 1; o <= 2; o <<= 1) {
            sA += __shfl_xor_sync(0xffffffffu, sA, o);
            sB += __shfl_xor_sync(0xffffffffu, sB, o);
        }
        mA = mA2; mB = mB2;
        lA = lA * alA + sA;
        lB = lB * alB + sB;

        #pragma unroll
        for (int t = 0; t < 8; t++) {
            oc[t][0] *= alA; oc[t][1] *= alA;
            oc[t][2] *= alB; oc[t][3] *= alB;
        }

        // ---- O += P * V : P packs directly into fp16 A-frags; V pre-transposed ----
        #pragma unroll
        for (int kk = 0; kk < 4; kk++) {
            uint32_t ap[4];
            ap[0] = pack_h2(sc[2 * kk][0],     sc[2 * kk][1]);
            ap[1] = pack_h2(sc[2 * kk][2],     sc[2 * kk][3]);
            ap[2] = pack_h2(sc[2 * kk + 1][0], sc[2 * kk + 1][1]);
            ap[3] = pack_h2(sc[2 * kk + 1][2], sc[2 * kk + 1][3]);
            #pragma unroll
            for (int nt = 0; nt < 8; nt++) {
                const __half* vp = V + (nt * 8 + g) * AT_LD + kk * 16 + c2;
                uint32_t b0 = *reinterpret_cast<const uint32_t*>(vp);
                uint32_t b1 = *reinterpret_cast<const uint32_t*>(vp + 8);
                mma_f16(oc[nt], ap, b0, b1);
            }
        }
    }

    // ---- epilogue: out = half(O / l) ----
    const float iA = 1.0f / lA;
    const float iB = 1.0f / lB;
    __half* ob = out + (size_t)(b * SEQ + qt * 64 + w * 16 + g) * CH + h * 64 + c2;
    #pragma unroll
    for (int t = 0; t < 8; t++) {
        __half2 vA = __floats2half2_rn(oc[t][0] * iA, oc[t][1] * iA);
        __half2 vB = __floats2half2_rn(oc[t][2] * iB, oc[t][3] * iB);
        *reinterpret_cast<__half2*>(ob + t * 8) = vA;
        *reinterpret_cast<__half2*>(ob + 8 * CH + t * 8) = vB;
    }
}

// ---------------- launch ----------------
extern "C" void kernel_launch(void* const* d_in, const int* in_sizes, int n_in,
                              void* d_out, int out_size)
{
    const float* x     = (const float*)d_in[0];
    const float* w_qkv = (const float*)d_in[1];
    const float* w_out = (const float*)d_in[2];
    float* out = (float*)d_out;

    __half *qkvh, *attnh, *xh, *wqkvT, *woutT, *vT;
    cudaGetSymbolAddress((void**)&qkvh,  g_qkvh);
    cudaGetSymbolAddress((void**)&attnh, g_attnh);
    cudaGetSymbolAddress((void**)&xh,    g_xh);
    cudaGetSymbolAddress((void**)&wqkvT, g_wqkvT);
    cudaGetSymbolAddress((void**)&woutT, g_woutT);
    cudaGetSymbolAddress((void**)&vT,    g_vT);

    cudaFuncSetAttribute(gemm_f16_kernel<true>,  cudaFuncAttributeMaxDynamicSharedMemorySize, GEMM_SMEM);
    cudaFuncSetAttribute(gemm_f16_kernel<false>, cudaFuncAttributeMaxDynamicSharedMemorySize, GEMM_SMEM);
    cudaFuncSetAttribute(attn_kernel, cudaFuncAttributeMaxDynamicSharedMemorySize, AT_SMEM_BYTES);

    // 0) fp16 conversions: x, transposed weights
    f2h_kernel<<<512, 256>>>((const float4*)x, (__half2*)xh, (ROWS * CH) / 4);
    {
        dim3 blk(32, 8);
        wtrans_kernel<<<dim3(C3 / 32, CH / 32), blk>>>(w_qkv, wqkvT, CH, C3);
        wtrans_kernel<<<dim3(CH / 32, CH / 32), blk>>>(w_out, woutT, CH, CH);
    }

    // 1) qkv = x @ w_qkv  -> fp16 [8192 x 3072]
    gemm_f16_kernel<true><<<dim3(C3 / GTN, ROWS / GTM), 256, GEMM_SMEM>>>(
        xh, wqkvT, qkvh, C3, CH);

    // 1b) transpose V: vT[bh][d][t]
    {
        dim3 blk(32, 8);
        vtrans_kernel<<<dim3(SEQ / 32, DK / 32, BATCH * NHEAD), blk>>>(qkvh, vT);
    }

    // 2) flash attention -> fp16
    attn_kernel<<<dim3(SEQ / 64, BATCH * NHEAD), 128, AT_SMEM_BYTES>>>(qkvh, vT, attnh);

    // 3) out = attn @ w_out -> fp32 [8192 x 1024]
    gemm_f16_kernel<false><<<dim3(CH / GTN, ROWS / GTM), 256, GEMM_SMEM>>>(
        attnh, woutT, out, CH, CH);
}

// round 6
// speedup vs baseline: 5.6838x; 1.1318x over previous
#include <cuda_runtime.h>
#include <cuda_fp16.h>
#include <math.h>
#include <stdint.h>

#define BATCH 4
#define SEQ   2048
#define CH    1024
#define NHEAD 16
#define DK    64
#define C3    3072
#define ROWS  (BATCH*SEQ)   // 8192

// ---------------- scratch ----------------
__device__ __align__(16) __half g_qkvh[(size_t)ROWS * C3];   // 48 MB
__device__ __align__(16) __half g_attnh[(size_t)ROWS * CH];  // 16 MB
__device__ __align__(16) __half g_xh[(size_t)ROWS * CH];     // 16 MB
__device__ __align__(16) __half g_wqkvT[(size_t)C3 * CH];    // 6 MB  [N,K]
__device__ __align__(16) __half g_woutT[(size_t)CH * CH];    // 2 MB
__device__ __align__(16) __half g_vT[(size_t)BATCH * NHEAD * DK * SEQ]; // 16 MB [bh][d][t]

// ---------------- helpers ----------------
__device__ __forceinline__ void cp_async16(void* smem_dst, const void* gmem_src) {
    unsigned s = (unsigned)__cvta_generic_to_shared(smem_dst);
    asm volatile("cp.async.cg.shared.global [%0], [%1], 16;\n" :: "r"(s), "l"(gmem_src));
}
__device__ __forceinline__ void cp_commit() {
    asm volatile("cp.async.commit_group;\n" ::);
}
template<int N>
__device__ __forceinline__ void cp_wait() {
    asm volatile("cp.async.wait_group %0;\n" :: "n"(N));
}
__device__ __forceinline__ void mma_f16(float c[4], const uint32_t a[4], uint32_t b0, uint32_t b1) {
    asm volatile(
        "mma.sync.aligned.m16n8k16.row.col.f32.f16.f16.f32 "
        "{%0,%1,%2,%3}, {%4,%5,%6,%7}, {%8,%9}, {%0,%1,%2,%3};"
        : "+f"(c[0]), "+f"(c[1]), "+f"(c[2]), "+f"(c[3])
        : "r"(a[0]), "r"(a[1]), "r"(a[2]), "r"(a[3]), "r"(b0), "r"(b1));
}
__device__ __forceinline__ uint32_t pack_h2(float x, float y) {
    __half2 h = __floats2half2_rn(x, y);
    return *reinterpret_cast<uint32_t*>(&h);
}
__device__ __forceinline__ void ldm_x4(uint32_t& r0, uint32_t& r1, uint32_t& r2, uint32_t& r3,
                                       const __half* p) {
    uint32_t addr = (uint32_t)__cvta_generic_to_shared(p);
    asm volatile("ldmatrix.sync.aligned.m8n8.x4.shared.b16 {%0,%1,%2,%3}, [%4];"
        : "=r"(r0), "=r"(r1), "=r"(r2), "=r"(r3) : "r"(addr));
}

// ---------------- pre-pass kernels ----------------
__global__ void f2h_kernel(const float4* __restrict__ in, __half2* __restrict__ out, int n4) {
    int i = blockIdx.x * blockDim.x + threadIdx.x;
    int stride = gridDim.x * blockDim.x;
    for (; i < n4; i += stride) {
        float4 v = in[i];
        out[2 * i]     = __floats2half2_rn(v.x, v.y);
        out[2 * i + 1] = __floats2half2_rn(v.z, v.w);
    }
}

__global__ void wtrans_kernel(const float* __restrict__ in, __half* __restrict__ out,
                              int R, int C) {
    __shared__ float t[32][33];
    int bx = blockIdx.x * 32;
    int by = blockIdx.y * 32;
    #pragma unroll
    for (int j = 0; j < 32; j += 8)
        t[threadIdx.y + j][threadIdx.x] = in[(size_t)(by + threadIdx.y + j) * C + bx + threadIdx.x];
    __syncthreads();
    #pragma unroll
    for (int j = 0; j < 32; j += 8)
        out[(size_t)(bx + threadIdx.y + j) * R + by + threadIdx.x] =
            __float2half(t[threadIdx.x][threadIdx.y + j]);
}

__global__ void vtrans_kernel(const __half* __restrict__ qkvh, __half* __restrict__ vT) {
    __shared__ __half s[32][34];
    const int bh = blockIdx.z;
    const int b = bh >> 4, h = bh & 15;
    const int t0 = blockIdx.x * 32;
    const int d0 = blockIdx.y * 32;
    #pragma unroll
    for (int j = 0; j < 32; j += 8)
        s[threadIdx.y + j][threadIdx.x] =
            qkvh[(size_t)(b * SEQ + t0 + threadIdx.y + j) * C3 + 2 * CH + h * 64 + d0 + threadIdx.x];
    __syncthreads();
    #pragma unroll
    for (int j = 0; j < 32; j += 8)
        vT[((size_t)bh * 64 + d0 + threadIdx.y + j) * SEQ + t0 + threadIdx.x] =
            s[threadIdx.x][threadIdx.y + j];
}

// ---------------- fp16 GEMM: C[M,N] = A[M,K] @ Bt[N,K]^T, fp32 accum ----------------
#define GTM 128
#define GTN 128
#define GTK 32
#define GLD 40
#define G_ASTG (128 * GLD)
#define G_STG  (2 * G_ASTG)
#define GSTAGES 4
#define GEMM_SMEM (GSTAGES * G_STG * 2)   // 81920 bytes

template<bool HALF_OUT>
__global__ void __launch_bounds__(256, 2) gemm_f16_kernel(
    const __half* __restrict__ A, const __half* __restrict__ Bt,
    void* __restrict__ Cout, int Ntot, int K)
{
    extern __shared__ __half sh[];
    const int tid = threadIdx.x;
    const int lane = tid & 31;
    const int wid = tid >> 5;
    const int wm = wid & 3;
    const int wn = wid >> 2;
    const int m0 = blockIdx.y * GTM;
    const int n0 = blockIdx.x * GTN;
    const int KT = K / GTK;
    const int g = lane >> 2;
    const int c2 = 2 * (lane & 3);

    // ldmatrix lane-address components
    const int a_row = lane & 15;             // A: rows 0..15 within m16 tile
    const int a_ko  = (lane >> 4) * 8;       // A: k offset 0/8
    const int b_row = ((lane >> 4) * 8) + (lane & 7);  // B: rows 0..15 within n16 pair
    const int b_ko  = ((lane >> 3) & 1) * 8;           // B: k offset 0/8

    auto fill = [&](int buf, int s) {
        __half* As = sh + buf * G_STG;
        __half* Bs = As + G_ASTG;
        const int k0 = s * GTK;
        #pragma unroll
        for (int j = 0; j < 2; j++) {
            int c = tid + j * 256;
            int row = c >> 2, ch = (c & 3) << 3;
            cp_async16(As + row * GLD + ch, A + (size_t)(m0 + row) * K + k0 + ch);
        }
        #pragma unroll
        for (int j = 0; j < 2; j++) {
            int c = tid + j * 256;
            int row = c >> 2, ch = (c & 3) << 3;
            cp_async16(Bs + row * GLD + ch, Bt + (size_t)(n0 + row) * K + k0 + ch);
        }
    };

    float acc[2][8][4];
    #pragma unroll
    for (int i = 0; i < 2; i++)
        #pragma unroll
        for (int j = 0; j < 8; j++)
            #pragma unroll
            for (int e = 0; e < 4; e++) acc[i][j][e] = 0.0f;

    fill(0, 0); cp_commit();
    fill(1, 1); cp_commit();
    fill(2, 2); cp_commit();

    for (int s = 0; s < KT; s++) {
        if (s + 3 < KT) fill((s + 3) & 3, s + 3);
        cp_commit();
        cp_wait<2>();
        __syncthreads();

        const __half* As = sh + (s & 3) * G_STG;
        const __half* Bs = As + G_ASTG;

        #pragma unroll
        for (int kk = 0; kk < 2; kk++) {
            uint32_t a[2][4];
            #pragma unroll
            for (int mt = 0; mt < 2; mt++)
                ldm_x4(a[mt][0], a[mt][1], a[mt][2], a[mt][3],
                       As + (wm * 32 + mt * 16 + a_row) * GLD + kk * 16 + a_ko);

            uint32_t bf[8][2];
            #pragma unroll
            for (int np = 0; np < 4; np++)
                ldm_x4(bf[2 * np][0], bf[2 * np][1], bf[2 * np + 1][0], bf[2 * np + 1][1],
                       Bs + (wn * 64 + np * 16 + b_row) * GLD + kk * 16 + b_ko);

            #pragma unroll
            for (int nt = 0; nt < 8; nt++) {
                mma_f16(acc[0][nt], a[0], bf[nt][0], bf[nt][1]);
                mma_f16(acc[1][nt], a[1], bf[nt][0], bf[nt][1]);
            }
        }
        __syncthreads();
    }

    // epilogue
    #pragma unroll
    for (int mt = 0; mt < 2; mt++) {
        #pragma unroll
        for (int nt = 0; nt < 8; nt++) {
            const int row = m0 + wm * 32 + mt * 16 + g;
            const int col = n0 + wn * 64 + nt * 8 + c2;
            if (HALF_OUT) {
                __half* Ch = (__half*)Cout;
                *reinterpret_cast<__half2*>(Ch + (size_t)row * Ntot + col) =
                    __floats2half2_rn(acc[mt][nt][0], acc[mt][nt][1]);
                *reinterpret_cast<__half2*>(Ch + (size_t)(row + 8) * Ntot + col) =
                    __floats2half2_rn(acc[mt][nt][2], acc[mt][nt][3]);
            } else {
                float* Cf = (float*)Cout;
                *reinterpret_cast<float2*>(Cf + (size_t)row * Ntot + col) =
                    make_float2(acc[mt][nt][0], acc[mt][nt][1]);
                *reinterpret_cast<float2*>(Cf + (size_t)(row + 8) * Ntot + col) =
                    make_float2(acc[mt][nt][2], acc[mt][nt][3]);
            }
        }
    }
}

// ---------------- Flash attention, fp16 mma + ldmatrix ----------------
#define AT_LD 72
#define AT_TILE (64 * AT_LD)
#define AT_BUF (2 * AT_TILE)
#define AT_SMEM_HALVES (2 * AT_BUF + AT_TILE)
#define AT_SMEM_BYTES (AT_SMEM_HALVES * 2)   // 46080

__global__ void __launch_bounds__(128, 3) attn_kernel(
    const __half* __restrict__ qkvh, const __half* __restrict__ vT,
    __half* __restrict__ out)
{
    extern __shared__ __half smh[];
    const int tid = threadIdx.x;
    const int lane = tid & 31;
    const int w = tid >> 5;
    const int g = lane >> 2;
    const int c2 = 2 * (lane & 3);
    const int qt = blockIdx.x;
    const int bh = blockIdx.y;
    const int b = bh >> 4;
    const int h = bh & 15;

    const int a_row = lane & 15;
    const int a_ko  = (lane >> 4) * 8;
    const int b_row = ((lane >> 4) * 8) + (lane & 7);
    const int b_ko  = ((lane >> 3) & 1) * 8;

    __half* Qs = smh + 2 * AT_BUF;

    auto fill = [&](int buf, int j) {
        __half* K = smh + buf * AT_BUF;
        __half* V = K + AT_TILE;
        const __half* kg = qkvh + (size_t)(b * SEQ + j * 64) * C3 + CH + h * 64;
        const __half* vg = vT + ((size_t)bh * 64) * SEQ + j * 64;
        #pragma unroll
        for (int i = 0; i < 4; i++) {
            int f = tid + i * 128;
            int r = f >> 3, ch = (f & 7) << 3;
            cp_async16(K + r * AT_LD + ch, kg + (size_t)r * C3 + ch);
            cp_async16(V + r * AT_LD + ch, vg + (size_t)r * SEQ + ch);
        }
    };

    fill(0, 0);
    cp_commit();

    {
        const __half* gq = qkvh + (size_t)(b * SEQ + qt * 64) * C3 + h * 64;
        #pragma unroll
        for (int f = tid; f < 512; f += 128) {
            int r = f >> 3, ch = (f & 7) << 3;
            *reinterpret_cast<uint4*>(Qs + r * AT_LD + ch) =
                *reinterpret_cast<const uint4*>(gq + (size_t)r * C3 + ch);
        }
    }
    __syncthreads();

    // Q a-fragments via ldmatrix, scaled by 1/8 (exact in fp16)
    uint32_t aq[4][4];
    {
        const __half2 sc8 = __float2half2_rn(0.125f);
        #pragma unroll
        for (int kk = 0; kk < 4; kk++) {
            ldm_x4(aq[kk][0], aq[kk][1], aq[kk][2], aq[kk][3],
                   Qs + (w * 16 + a_row) * AT_LD + kk * 16 + a_ko);
            #pragma unroll
            for (int e = 0; e < 4; e++) {
                __half2 v = *reinterpret_cast<__half2*>(&aq[kk][e]);
                v = __hmul2(v, sc8);
                aq[kk][e] = *reinterpret_cast<uint32_t*>(&v);
            }
        }
    }

    float oc[8][4];
    #pragma unroll
    for (int t = 0; t < 8; t++)
        #pragma unroll
        for (int e = 0; e < 4; e++) oc[t][e] = 0.0f;
    float mA = -INFINITY, mB = -INFINITY, lA = 0.0f, lB = 0.0f;
    const int rlocA = w * 16 + g;

    for (int j = 0; j <= qt; j++) {
        cp_wait<0>();
        __syncthreads();
        if (j < qt) { fill((j + 1) & 1, j + 1); cp_commit(); }

        const __half* K = smh + (j & 1) * AT_BUF;
        const __half* V = K + AT_TILE;

        // ---- S = Q*K^T ----
        float sc[8][4];
        #pragma unroll
        for (int t = 0; t < 8; t++)
            #pragma unroll
            for (int e = 0; e < 4; e++) sc[t][e] = 0.0f;

        #pragma unroll
        for (int kk = 0; kk < 4; kk++) {
            uint32_t kb[8][2];
            #pragma unroll
            for (int np = 0; np < 4; np++)
                ldm_x4(kb[2 * np][0], kb[2 * np][1], kb[2 * np + 1][0], kb[2 * np + 1][1],
                       K + (np * 16 + b_row) * AT_LD + kk * 16 + b_ko);
            #pragma unroll
            for (int nt = 0; nt < 8; nt++)
                mma_f16(sc[nt], aq[kk], kb[nt][0], kb[nt][1]);
        }

        // ---- causal mask on diagonal tile ----
        if (j == qt) {
            #pragma unroll
            for (int t = 0; t < 8; t++) {
                int cc0 = t * 8 + c2;
                int cc1 = cc0 + 1;
                if (cc0 > rlocA)     sc[t][0] = -INFINITY;
                if (cc1 > rlocA)     sc[t][1] = -INFINITY;
                if (cc0 > rlocA + 8) sc[t][2] = -INFINITY;
                if (cc1 > rlocA + 8) sc[t][3] = -INFINITY;
            }
        }

        // ---- online softmax ----
        float mxA = -INFINITY, mxB = -INFINITY;
        #pragma unroll
        for (int t = 0; t < 8; t++) {
            mxA = fmaxf(mxA, fmaxf(sc[t][0], sc[t][1]));
            mxB = fmaxf(mxB, fmaxf(sc[t][2], sc[t][3]));
        }
        #pragma unroll
        for (int o = 1; o <= 2; o <<= 1) {
            mxA = fmaxf(mxA, __shfl_xor_sync(0xffffffffu, mxA, o));
            mxB = fmaxf(mxB, __shfl_xor_sync(0xffffffffu, mxB, o));
        }
        const float mA2 = fmaxf(mA, mxA);
        const float mB2 = fmaxf(mB, mxB);
        const float alA = __expf(mA - mA2);
        const float alB = __expf(mB - mB2);

        float sA = 0.0f, sB = 0.0f;
        #pragma unroll
        for (int t = 0; t < 8; t++) {
            sc[t][0] = __expf(sc[t][0] - mA2);
            sc[t][1] = __expf(sc[t][1] - mA2);
            sc[t][2] = __expf(sc[t][2] - mB2);
            sc[t][3] = __expf(sc[t][3] - mB2);
            sA += sc[t][0] + sc[t][1];
            sB += sc[t][2] + sc[t][3];
        }
        #pragma unroll
        for (int o = 1; o <= 2; o <<= 1) {
            sA += __shfl_xor_sync(0xffffffffu, sA, o);
            sB += __shfl_xor_sync(0xffffffffu, sB, o);
        }
        mA = mA2; mB = mB2;
        lA = lA * alA + sA;
        lB = lB * alB + sB;

        #pragma unroll
        for (int t = 0; t < 8; t++) {
            oc[t][0] *= alA; oc[t][1] *= alA;
            oc[t][2] *= alB; oc[t][3] *= alB;
        }

        // ---- O += P * V ----
        #pragma unroll
        for (int kk = 0; kk < 4; kk++) {
            uint32_t ap[4];
            ap[0] = pack_h2(sc[2 * kk][0],     sc[2 * kk][1]);
            ap[1] = pack_h2(sc[2 * kk][2],     sc[2 * kk][3]);
            ap[2] = pack_h2(sc[2 * kk + 1][0], sc[2 * kk + 1][1]);
            ap[3] = pack_h2(sc[2 * kk + 1][2], sc[2 * kk + 1][3]);
            uint32_t vb[8][2];
            #pragma unroll
            for (int np = 0; np < 4; np++)
                ldm_x4(vb[2 * np][0], vb[2 * np][1], vb[2 * np + 1][0], vb[2 * np + 1][1],
                       V + (np * 16 + b_row) * AT_LD + kk * 16 + b_ko);
            #pragma unroll
            for (int nt = 0; nt < 8; nt++)
                mma_f16(oc[nt], ap, vb[nt][0], vb[nt][1]);
        }
    }

    // ---- epilogue ----
    const float iA = 1.0f / lA;
    const float iB = 1.0f / lB;
    __half* ob = out + (size_t)(b * SEQ + qt * 64 + w * 16 + g) * CH + h * 64 + c2;
    #pragma unroll
    for (int t = 0; t < 8; t++) {
        *reinterpret_cast<__half2*>(ob + t * 8) =
            __floats2half2_rn(oc[t][0] * iA, oc[t][1] * iA);
        *reinterpret_cast<__half2*>(ob + 8 * CH + t * 8) =
            __floats2half2_rn(oc[t][2] * iB, oc[t][3] * iB);
    }
}

// ---------------- launch ----------------
extern "C" void kernel_launch(void* const* d_in, const int* in_sizes, int n_in,
                              void* d_out, int out_size)
{
    const float* x     = (const float*)d_in[0];
    const float* w_qkv = (const float*)d_in[1];
    const float* w_out = (const float*)d_in[2];
    float* out = (float*)d_out;

    __half *qkvh, *attnh, *xh, *wqkvT, *woutT, *vT;
    cudaGetSymbolAddress((void**)&qkvh,  g_qkvh);
    cudaGetSymbolAddress((void**)&attnh, g_attnh);
    cudaGetSymbolAddress((void**)&xh,    g_xh);
    cudaGetSymbolAddress((void**)&wqkvT, g_wqkvT);
    cudaGetSymbolAddress((void**)&woutT, g_woutT);
    cudaGetSymbolAddress((void**)&vT,    g_vT);

    cudaFuncSetAttribute(gemm_f16_kernel<true>,  cudaFuncAttributeMaxDynamicSharedMemorySize, GEMM_SMEM);
    cudaFuncSetAttribute(gemm_f16_kernel<false>, cudaFuncAttributeMaxDynamicSharedMemorySize, GEMM_SMEM);
    cudaFuncSetAttribute(attn_kernel, cudaFuncAttributeMaxDynamicSharedMemorySize, AT_SMEM_BYTES);

    f2h_kernel<<<512, 256>>>((const float4*)x, (__half2*)xh, (ROWS * CH) / 4);
    {
        dim3 blk(32, 8);
        wtrans_kernel<<<dim3(C3 / 32, CH / 32), blk>>>(w_qkv, wqkvT, CH, C3);
        wtrans_kernel<<<dim3(CH / 32, CH / 32), blk>>>(w_out, woutT, CH, CH);
    }

    gemm_f16_kernel<true><<<dim3(C3 / GTN, ROWS / GTM), 256, GEMM_SMEM>>>(
        xh, wqkvT, qkvh, C3, CH);

    {
        dim3 blk(32, 8);
        vtrans_kernel<<<dim3(SEQ / 32, DK / 32, BATCH * NHEAD), blk>>>(qkvh, vT);
    }

    attn_kernel<<<dim3(SEQ / 64, BATCH * NHEAD), 128, AT_SMEM_BYTES>>>(qkvh, vT, attnh);

    gemm_f16_kernel<false><<<dim3(CH / GTN, ROWS / GTM), 256, GEMM_SMEM>>>(
        attnh, woutT, out, CH, CH);
}

// round 7
// speedup vs baseline: 5.8904x; 1.0363x over previous
#include <cuda_runtime.h>
#include <cuda_fp16.h>
#include <math.h>
#include <stdint.h>

#define BATCH 4
#define SEQ   2048
#define CH    1024
#define NHEAD 16
#define DK    64
#define C3    3072
#define ROWS  (BATCH*SEQ)   // 8192

// ---------------- scratch ----------------
__device__ __align__(16) __half g_qkvh[(size_t)ROWS * C3];   // 48 MB
__device__ __align__(16) __half g_attnh[(size_t)ROWS * CH];  // 16 MB
__device__ __align__(16) __half g_xh[(size_t)ROWS * CH];     // 16 MB
__device__ __align__(16) __half g_wqkvT[(size_t)C3 * CH];    // 6 MB  [N,K]
__device__ __align__(16) __half g_woutT[(size_t)CH * CH];    // 2 MB
__device__ __align__(16) __half g_vT[(size_t)BATCH * NHEAD * DK * SEQ]; // 16 MB [bh][d][t]

// ---------------- helpers ----------------
__device__ __forceinline__ void cp_async16(void* smem_dst, const void* gmem_src) {
    unsigned s = (unsigned)__cvta_generic_to_shared(smem_dst);
    asm volatile("cp.async.cg.shared.global [%0], [%1], 16;\n" :: "r"(s), "l"(gmem_src));
}
__device__ __forceinline__ void cp_commit() {
    asm volatile("cp.async.commit_group;\n" ::);
}
template<int N>
__device__ __forceinline__ void cp_wait() {
    asm volatile("cp.async.wait_group %0;\n" :: "n"(N));
}
__device__ __forceinline__ void mma_f16(float c[4], const uint32_t a[4], uint32_t b0, uint32_t b1) {
    asm volatile(
        "mma.sync.aligned.m16n8k16.row.col.f32.f16.f16.f32 "
        "{%0,%1,%2,%3}, {%4,%5,%6,%7}, {%8,%9}, {%0,%1,%2,%3};"
        : "+f"(c[0]), "+f"(c[1]), "+f"(c[2]), "+f"(c[3])
        : "r"(a[0]), "r"(a[1]), "r"(a[2]), "r"(a[3]), "r"(b0), "r"(b1));
}
__device__ __forceinline__ uint32_t pack_h2(float x, float y) {
    __half2 h = __floats2half2_rn(x, y);
    return *reinterpret_cast<uint32_t*>(&h);
}
__device__ __forceinline__ void ldm_x4(uint32_t& r0, uint32_t& r1, uint32_t& r2, uint32_t& r3,
                                       const __half* p) {
    uint32_t addr = (uint32_t)__cvta_generic_to_shared(p);
    asm volatile("ldmatrix.sync.aligned.m8n8.x4.shared.b16 {%0,%1,%2,%3}, [%4];"
        : "=r"(r0), "=r"(r1), "=r"(r2), "=r"(r3) : "r"(addr));
}

// ---------------- pre-pass kernels ----------------
__global__ void f2h_kernel(const float4* __restrict__ in, __half2* __restrict__ out, int n4) {
    int i = blockIdx.x * blockDim.x + threadIdx.x;
    int stride = gridDim.x * blockDim.x;
    for (; i < n4; i += stride) {
        float4 v = in[i];
        out[2 * i]     = __floats2half2_rn(v.x, v.y);
        out[2 * i + 1] = __floats2half2_rn(v.z, v.w);
    }
}

__global__ void wtrans_kernel(const float* __restrict__ in, __half* __restrict__ out,
                              int R, int C) {
    __shared__ float t[32][33];
    int bx = blockIdx.x * 32;
    int by = blockIdx.y * 32;
    #pragma unroll
    for (int j = 0; j < 32; j += 8)
        t[threadIdx.y + j][threadIdx.x] = in[(size_t)(by + threadIdx.y + j) * C + bx + threadIdx.x];
    __syncthreads();
    #pragma unroll
    for (int j = 0; j < 32; j += 8)
        out[(size_t)(bx + threadIdx.y + j) * R + by + threadIdx.x] =
            __float2half(t[threadIdx.x][threadIdx.y + j]);
}

__global__ void vtrans_kernel(const __half* __restrict__ qkvh, __half* __restrict__ vT) {
    __shared__ __half s[32][34];
    const int bh = blockIdx.z;
    const int b = bh >> 4, h = bh & 15;
    const int t0 = blockIdx.x * 32;
    const int d0 = blockIdx.y * 32;
    #pragma unroll
    for (int j = 0; j < 32; j += 8)
        s[threadIdx.y + j][threadIdx.x] =
            qkvh[(size_t)(b * SEQ + t0 + threadIdx.y + j) * C3 + 2 * CH + h * 64 + d0 + threadIdx.x];
    __syncthreads();
    #pragma unroll
    for (int j = 0; j < 32; j += 8)
        vT[((size_t)bh * 64 + d0 + threadIdx.y + j) * SEQ + t0 + threadIdx.x] =
            s[threadIdx.x][threadIdx.y + j];
}

// ---------------- fp16 GEMM: C[M,N] = A[M,K] @ Bt[N,K]^T ----------------
// 128x128 tile, TK=64, 3-stage cp.async, single __syncthreads per stage.
#define GTM 128
#define GTN 128
#define GTK 64
#define GLD 72
#define G_ASTG (128 * GLD)           // 9216 halves
#define G_STG  (2 * G_ASTG)          // 18432 halves
#define GSTAGES 3
#define GEMM_SMEM (GSTAGES * G_STG * 2)   // 110592 bytes

template<bool HALF_OUT>
__global__ void __launch_bounds__(256, 2) gemm_f16_kernel(
    const __half* __restrict__ A, const __half* __restrict__ Bt,
    void* __restrict__ Cout, int Ntot, int K)
{
    extern __shared__ __half sh[];
    const int tid = threadIdx.x;
    const int lane = tid & 31;
    const int wid = tid >> 5;
    const int wm = wid & 3;
    const int wn = wid >> 2;
    const int m0 = blockIdx.y * GTM;
    const int n0 = blockIdx.x * GTN;
    const int KT = K / GTK;
    const int g = lane >> 2;
    const int c2 = 2 * (lane & 3);

    const int a_row = lane & 15;
    const int a_ko  = (lane >> 4) * 8;
    const int b_row = ((lane >> 4) * 8) + (lane & 7);
    const int b_ko  = ((lane >> 3) & 1) * 8;

    auto fill = [&](int buf, int s) {
        __half* As = sh + buf * G_STG;
        __half* Bs = As + G_ASTG;
        const int k0 = s * GTK;
        #pragma unroll
        for (int j = 0; j < 4; j++) {
            int c = tid + j * 256;
            int row = c >> 3, ch = (c & 7) << 3;
            cp_async16(As + row * GLD + ch, A + (size_t)(m0 + row) * K + k0 + ch);
        }
        #pragma unroll
        for (int j = 0; j < 4; j++) {
            int c = tid + j * 256;
            int row = c >> 3, ch = (c & 7) << 3;
            cp_async16(Bs + row * GLD + ch, Bt + (size_t)(n0 + row) * K + k0 + ch);
        }
    };

    float acc[2][8][4];
    #pragma unroll
    for (int i = 0; i < 2; i++)
        #pragma unroll
        for (int j = 0; j < 8; j++)
            #pragma unroll
            for (int e = 0; e < 4; e++) acc[i][j][e] = 0.0f;

    fill(0, 0); cp_commit();
    fill(1, 1); cp_commit();

    int buf = 0, pbuf = 2;
    for (int s = 0; s < KT; s++) {
        cp_wait<1>();
        __syncthreads();
        if (s + 2 < KT) fill(pbuf, s + 2);
        cp_commit();

        const __half* As = sh + buf * G_STG;
        const __half* Bs = As + G_ASTG;

        #pragma unroll
        for (int kk = 0; kk < 4; kk++) {
            uint32_t a[2][4];
            #pragma unroll
            for (int mt = 0; mt < 2; mt++)
                ldm_x4(a[mt][0], a[mt][1], a[mt][2], a[mt][3],
                       As + (wm * 32 + mt * 16 + a_row) * GLD + kk * 16 + a_ko);

            uint32_t bf[8][2];
            #pragma unroll
            for (int np = 0; np < 4; np++)
                ldm_x4(bf[2 * np][0], bf[2 * np][1], bf[2 * np + 1][0], bf[2 * np + 1][1],
                       Bs + (wn * 64 + np * 16 + b_row) * GLD + kk * 16 + b_ko);

            #pragma unroll
            for (int nt = 0; nt < 8; nt++) {
                mma_f16(acc[0][nt], a[0], bf[nt][0], bf[nt][1]);
                mma_f16(acc[1][nt], a[1], bf[nt][0], bf[nt][1]);
            }
        }
        buf = (buf == 2) ? 0 : buf + 1;
        pbuf = (pbuf == 2) ? 0 : pbuf + 1;
    }

    #pragma unroll
    for (int mt = 0; mt < 2; mt++) {
        #pragma unroll
        for (int nt = 0; nt < 8; nt++) {
            const int row = m0 + wm * 32 + mt * 16 + g;
            const int col = n0 + wn * 64 + nt * 8 + c2;
            if (HALF_OUT) {
                __half* Ch = (__half*)Cout;
                *reinterpret_cast<__half2*>(Ch + (size_t)row * Ntot + col) =
                    __floats2half2_rn(acc[mt][nt][0], acc[mt][nt][1]);
                *reinterpret_cast<__half2*>(Ch + (size_t)(row + 8) * Ntot + col) =
                    __floats2half2_rn(acc[mt][nt][2], acc[mt][nt][3]);
            } else {
                float* Cf = (float*)Cout;
                *reinterpret_cast<float2*>(Cf + (size_t)row * Ntot + col) =
                    make_float2(acc[mt][nt][0], acc[mt][nt][1]);
                *reinterpret_cast<float2*>(Cf + (size_t)(row + 8) * Ntot + col) =
                    make_float2(acc[mt][nt][2], acc[mt][nt][3]);
            }
        }
    }
}

// ---------------- Flash attention: 128 q-rows, 8 warps, fp16 mma + ldmatrix ----------------
#define BQ 128
#define AT_LD 72
#define KV_TILE (64 * AT_LD)                  // 4608 halves (one 64x64 operand)
#define AT_BUF (2 * KV_TILE)                  // K+V per stage = 9216
#define AT_SMEM_HALVES (2 * AT_BUF + BQ * AT_LD)  // 27648
#define AT_SMEM_BYTES (AT_SMEM_HALVES * 2)    // 55296

__global__ void __launch_bounds__(256, 2) attn_kernel(
    const __half* __restrict__ qkvh, const __half* __restrict__ vT,
    __half* __restrict__ out)
{
    extern __shared__ __half smh[];
    const int tid = threadIdx.x;
    const int lane = tid & 31;
    const int w = tid >> 5;                 // 0..7, warp owns q-rows [16w, 16w+16)
    const int g = lane >> 2;
    const int c2 = 2 * (lane & 3);
    const int qt = gridDim.x - 1 - blockIdx.x;   // heavy q-tiles first
    const int bh = blockIdx.y;
    const int b = bh >> 4;
    const int h = bh & 15;

    const int a_row = lane & 15;
    const int a_ko  = (lane >> 4) * 8;
    const int b_row = ((lane >> 4) * 8) + (lane & 7);
    const int b_ko  = ((lane >> 3) & 1) * 8;

    __half* Qs = smh + 2 * AT_BUF;
    const int NJ = 2 * qt + 2;                  // 64-key tiles covering [0, 128qt+128)

    auto fill = [&](int buf, int j) {
        __half* K = smh + buf * AT_BUF;
        __half* V = K + KV_TILE;
        const __half* kg = qkvh + (size_t)(b * SEQ + j * 64) * C3 + CH + h * 64;
        const __half* vg = vT + ((size_t)bh * 64) * SEQ + j * 64;
        #pragma unroll
        for (int i = 0; i < 2; i++) {
            int f = tid + i * 256;
            int r = f >> 3, ch = (f & 7) << 3;
            cp_async16(K + r * AT_LD + ch, kg + (size_t)r * C3 + ch);
            cp_async16(V + r * AT_LD + ch, vg + (size_t)r * SEQ + ch);
        }
    };

    fill(0, 0);
    cp_commit();

    // Q tile: 128 rows
    {
        const __half* gq = qkvh + (size_t)(b * SEQ + qt * BQ) * C3 + h * 64;
        #pragma unroll
        for (int f = tid; f < 1024; f += 256) {
            int r = f >> 3, ch = (f & 7) << 3;
            *reinterpret_cast<uint4*>(Qs + r * AT_LD + ch) =
                *reinterpret_cast<const uint4*>(gq + (size_t)r * C3 + ch);
        }
    }
    __syncthreads();

    // Q a-fragments (scaled by 1/8, exact)
    uint32_t aq[4][4];
    {
        const __half2 sc8 = __float2half2_rn(0.125f);
        #pragma unroll
        for (int kk = 0; kk < 4; kk++) {
            ldm_x4(aq[kk][0], aq[kk][1], aq[kk][2], aq[kk][3],
                   Qs + (w * 16 + a_row) * AT_LD + kk * 16 + a_ko);
            #pragma unroll
            for (int e = 0; e < 4; e++) {
                __half2 v = *reinterpret_cast<__half2*>(&aq[kk][e]);
                v = __hmul2(v, sc8);
                aq[kk][e] = *reinterpret_cast<uint32_t*>(&v);
            }
        }
    }

    float oc[8][4];
    #pragma unroll
    for (int t = 0; t < 8; t++)
        #pragma unroll
        for (int e = 0; e < 4; e++) oc[t][e] = 0.0f;
    float mA = -INFINITY, mB = -INFINITY, lA = 0.0f, lB = 0.0f;

    const int qrow0 = qt * BQ + w * 16;   // warp's first global q row
    const int qA = qrow0 + g;             // accumulator row A (rows +0..); B = qA+8

    for (int j = 0; j < NJ; j++) {
        cp_wait<0>();
        __syncthreads();
        if (j + 1 < NJ) { fill((j + 1) & 1, j + 1); cp_commit(); }

        const int jbase = j * 64;
        if (jbase > qrow0 + 15) continue;   // tile fully above this warp's rows (warp-uniform)

        const __half* K = smh + (j & 1) * AT_BUF;
        const __half* V = K + KV_TILE;

        // ---- S = Q*K^T ----
        float sc[8][4];
        #pragma unroll
        for (int t = 0; t < 8; t++)
            #pragma unroll
            for (int e = 0; e < 4; e++) sc[t][e] = 0.0f;

        #pragma unroll
        for (int kk = 0; kk < 4; kk++) {
            uint32_t kb[8][2];
            #pragma unroll
            for (int np = 0; np < 4; np++)
                ldm_x4(kb[2 * np][0], kb[2 * np][1], kb[2 * np + 1][0], kb[2 * np + 1][1],
                       K + (np * 16 + b_row) * AT_LD + kk * 16 + b_ko);
            #pragma unroll
            for (int nt = 0; nt < 8; nt++)
                mma_f16(sc[nt], aq[kk], kb[nt][0], kb[nt][1]);
        }

        // ---- causal mask (global coords) ----
        if (jbase + 63 > qrow0) {
            #pragma unroll
            for (int t = 0; t < 8; t++) {
                int cc0 = jbase + t * 8 + c2;
                int cc1 = cc0 + 1;
                if (cc0 > qA)     sc[t][0] = -INFINITY;
                if (cc1 > qA)     sc[t][1] = -INFINITY;
                if (cc0 > qA + 8) sc[t][2] = -INFINITY;
                if (cc1 > qA + 8) sc[t][3] = -INFINITY;
            }
        }

        // ---- online softmax ----
        float mxA = -INFINITY, mxB = -INFINITY;
        #pragma unroll
        for (int t = 0; t < 8; t++) {
            mxA = fmaxf(mxA, fmaxf(sc[t][0], sc[t][1]));
            mxB = fmaxf(mxB, fmaxf(sc[t][2], sc[t][3]));
        }
        #pragma unroll
        for (int o = 1; o <= 2; o <<= 1) {
            mxA = fmaxf(mxA, __shfl_xor_sync(0xffffffffu, mxA, o));
            mxB = fmaxf(mxB, __shfl_xor_sync(0xffffffffu, mxB, o));
        }
        const float mA2 = fmaxf(mA, mxA);
        const float mB2 = fmaxf(mB, mxB);
        const float alA = __expf(mA - mA2);
        const float alB = __expf(mB - mB2);

        float sA = 0.0f, sB = 0.0f;
        #pragma unroll
        for (int t = 0; t < 8; t++) {
            sc[t][0] = __expf(sc[t][0] - mA2);
            sc[t][1] = __expf(sc[t][1] - mA2);
            sc[t][2] = __expf(sc[t][2] - mB2);
            sc[t][3] = __expf(sc[t][3] - mB2);
            sA += sc[t][0] + sc[t][1];
            sB += sc[t][2] + sc[t][3];
        }
        #pragma unroll
        for (int o = 1; o <= 2; o <<= 1) {
            sA += __shfl_xor_sync(0xffffffffu, sA, o);
            sB += __shfl_xor_sync(0xffffffffu, sB, o);
        }
        mA = mA2; mB = mB2;
        lA = lA * alA + sA;
        lB = lB * alB + sB;

        #pragma unroll
        for (int t = 0; t < 8; t++) {
            oc[t][0] *= alA; oc[t][1] *= alA;
            oc[t][2] *= alB; oc[t][3] *= alB;
        }

        // ---- O += P * V ----
        #pragma unroll
        for (int kk = 0; kk < 4; kk++) {
            uint32_t ap[4];
            ap[0] = pack_h2(sc[2 * kk][0],     sc[2 * kk][1]);
            ap[1] = pack_h2(sc[2 * kk][2],     sc[2 * kk][3]);
            ap[2] = pack_h2(sc[2 * kk + 1][0], sc[2 * kk + 1][1]);
            ap[3] = pack_h2(sc[2 * kk + 1][2], sc[2 * kk + 1][3]);
            uint32_t vb[8][2];
            #pragma unroll
            for (int np = 0; np < 4; np++)
                ldm_x4(vb[2 * np][0], vb[2 * np][1], vb[2 * np + 1][0], vb[2 * np + 1][1],
                       V + (np * 16 + b_row) * AT_LD + kk * 16 + b_ko);
            #pragma unroll
            for (int nt = 0; nt < 8; nt++)
                mma_f16(oc[nt], ap, vb[nt][0], vb[nt][1]);
        }
    }

    // ---- epilogue ----
    const float iA = 1.0f / lA;
    const float iB = 1.0f / lB;
    __half* ob = out + (size_t)(b * SEQ + qt * BQ + w * 16 + g) * CH + h * 64 + c2;
    #pragma unroll
    for (int t = 0; t < 8; t++) {
        *reinterpret_cast<__half2*>(ob + t * 8) =
            __floats2half2_rn(oc[t][0] * iA, oc[t][1] * iA);
        *reinterpret_cast<__half2*>(ob + 8 * CH + t * 8) =
            __floats2half2_rn(oc[t][2] * iB, oc[t][3] * iB);
    }
}

// ---------------- launch ----------------
extern "C" void kernel_launch(void* const* d_in, const int* in_sizes, int n_in,
                              void* d_out, int out_size)
{
    const float* x     = (const float*)d_in[0];
    const float* w_qkv = (const float*)d_in[1];
    const float* w_out = (const float*)d_in[2];
    float* out = (float*)d_out;

    __half *qkvh, *attnh, *xh, *wqkvT, *woutT, *vT;
    cudaGetSymbolAddress((void**)&qkvh,  g_qkvh);
    cudaGetSymbolAddress((void**)&attnh, g_attnh);
    cudaGetSymbolAddress((void**)&xh,    g_xh);
    cudaGetSymbolAddress((void**)&wqkvT, g_wqkvT);
    cudaGetSymbolAddress((void**)&woutT, g_woutT);
    cudaGetSymbolAddress((void**)&vT,    g_vT);

    cudaFuncSetAttribute(gemm_f16_kernel<true>,  cudaFuncAttributeMaxDynamicSharedMemorySize, GEMM_SMEM);
    cudaFuncSetAttribute(gemm_f16_kernel<false>, cudaFuncAttributeMaxDynamicSharedMemorySize, GEMM_SMEM);
    cudaFuncSetAttribute(attn_kernel, cudaFuncAttributeMaxDynamicSharedMemorySize, AT_SMEM_BYTES);

    f2h_kernel<<<512, 256>>>((const float4*)x, (__half2*)xh, (ROWS * CH) / 4);
    {
        dim3 blk(32, 8);
        wtrans_kernel<<<dim3(C3 / 32, CH / 32), blk>>>(w_qkv, wqkvT, CH, C3);
        wtrans_kernel<<<dim3(CH / 32, CH / 32), blk>>>(w_out, woutT, CH, CH);
    }

    gemm_f16_kernel<true><<<dim3(C3 / GTN, ROWS / GTM), 256, GEMM_SMEM>>>(
        xh, wqkvT, qkvh, C3, CH);

    {
        dim3 blk(32, 8);
        vtrans_kernel<<<dim3(SEQ / 32, DK / 32, BATCH * NHEAD), blk>>>(qkvh, vT);
    }

    attn_kernel<<<dim3(SEQ / BQ, BATCH * NHEAD), 256, AT_SMEM_BYTES>>>(qkvh, vT, attnh);

    gemm_f16_kernel<false><<<dim3(CH / GTN, ROWS / GTM), 256, GEMM_SMEM>>>(
        attnh, woutT, out, CH, CH);
}

// round 8
// speedup vs baseline: 6.0897x; 1.0338x over previous
#include <cuda_runtime.h>
#include <cuda_fp16.h>
#include <math.h>
#include <stdint.h>

#define BATCH 4
#define SEQ   2048
#define CH    1024
#define NHEAD 16
#define DK    64
#define C3    3072
#define ROWS  (BATCH*SEQ)   // 8192

// ---------------- scratch ----------------
__device__ __align__(16) __half g_qkvh[(size_t)ROWS * C3];
__device__ __align__(16) __half g_attnh[(size_t)ROWS * CH];
__device__ __align__(16) __half g_xh[(size_t)ROWS * CH];
__device__ __align__(16) __half g_wqkvT[(size_t)C3 * CH];
__device__ __align__(16) __half g_woutT[(size_t)CH * CH];
__device__ __align__(16) __half g_vT[(size_t)BATCH * NHEAD * DK * SEQ];

// ---------------- helpers ----------------
__device__ __forceinline__ void cp_async16(void* smem_dst, const void* gmem_src) {
    unsigned s = (unsigned)__cvta_generic_to_shared(smem_dst);
    asm volatile("cp.async.cg.shared.global [%0], [%1], 16;\n" :: "r"(s), "l"(gmem_src));
}
__device__ __forceinline__ void cp_commit() {
    asm volatile("cp.async.commit_group;\n" ::);
}
template<int N>
__device__ __forceinline__ void cp_wait() {
    asm volatile("cp.async.wait_group %0;\n" :: "n"(N));
}
__device__ __forceinline__ void mma_f16(float c[4], const uint32_t a[4], uint32_t b0, uint32_t b1) {
    asm volatile(
        "mma.sync.aligned.m16n8k16.row.col.f32.f16.f16.f32 "
        "{%0,%1,%2,%3}, {%4,%5,%6,%7}, {%8,%9}, {%0,%1,%2,%3};"
        : "+f"(c[0]), "+f"(c[1]), "+f"(c[2]), "+f"(c[3])
        : "r"(a[0]), "r"(a[1]), "r"(a[2]), "r"(a[3]), "r"(b0), "r"(b1));
}
__device__ __forceinline__ uint32_t pack_h2(float x, float y) {
    __half2 h = __floats2half2_rn(x, y);
    return *reinterpret_cast<uint32_t*>(&h);
}
__device__ __forceinline__ void ldm_x4(uint32_t& r0, uint32_t& r1, uint32_t& r2, uint32_t& r3,
                                       const __half* p) {
    uint32_t addr = (uint32_t)__cvta_generic_to_shared(p);
    asm volatile("ldmatrix.sync.aligned.m8n8.x4.shared.b16 {%0,%1,%2,%3}, [%4];"
        : "=r"(r0), "=r"(r1), "=r"(r2), "=r"(r3) : "r"(addr));
}

// ---------------- pre-pass kernels ----------------
__global__ void f2h_kernel(const float4* __restrict__ in, __half2* __restrict__ out, int n4) {
    int i = blockIdx.x * blockDim.x + threadIdx.x;
    int stride = gridDim.x * blockDim.x;
    for (; i < n4; i += stride) {
        float4 v = in[i];
        out[2 * i]     = __floats2half2_rn(v.x, v.y);
        out[2 * i + 1] = __floats2half2_rn(v.z, v.w);
    }
}

__global__ void wtrans_kernel(const float* __restrict__ in, __half* __restrict__ out,
                              int R, int C) {
    __shared__ float t[32][33];
    int bx = blockIdx.x * 32;
    int by = blockIdx.y * 32;
    #pragma unroll
    for (int j = 0; j < 32; j += 8)
        t[threadIdx.y + j][threadIdx.x] = in[(size_t)(by + threadIdx.y + j) * C + bx + threadIdx.x];
    __syncthreads();
    #pragma unroll
    for (int j = 0; j < 32; j += 8)
        out[(size_t)(bx + threadIdx.y + j) * R + by + threadIdx.x] =
            __float2half(t[threadIdx.x][threadIdx.y + j]);
}

__global__ void vtrans_kernel(const __half* __restrict__ qkvh, __half* __restrict__ vT) {
    __shared__ __half s[32][34];
    const int bh = blockIdx.z;
    const int b = bh >> 4, h = bh & 15;
    const int t0 = blockIdx.x * 32;
    const int d0 = blockIdx.y * 32;
    #pragma unroll
    for (int j = 0; j < 32; j += 8)
        s[threadIdx.y + j][threadIdx.x] =
            qkvh[(size_t)(b * SEQ + t0 + threadIdx.y + j) * C3 + 2 * CH + h * 64 + d0 + threadIdx.x];
    __syncthreads();
    #pragma unroll
    for (int j = 0; j < 32; j += 8)
        vT[((size_t)bh * 64 + d0 + threadIdx.y + j) * SEQ + t0 + threadIdx.x] =
            s[threadIdx.x][threadIdx.y + j];
}

// ---------------- fp16 GEMM: C[M,N] = A[M,K] @ Bt[N,K]^T ----------------
// CTA 128x128, 4 warps of 64x64 each, TK=64, 2-stage cp.async.
#define GTM 128
#define GTN 128
#define GTK 64
#define GLD 72
#define G_ASTG (GTM * GLD)            // 9216 halves
#define G_STG  (2 * G_ASTG)           // 18432 halves
#define GEMM_SMEM (2 * G_STG * 2)     // 73728 bytes

template<bool HALF_OUT>
__global__ void __launch_bounds__(128, 2) gemm_f16_kernel(
    const __half* __restrict__ A, const __half* __restrict__ Bt,
    void* __restrict__ Cout, int Ntot, int K)
{
    extern __shared__ __half sh[];
    const int tid = threadIdx.x;
    const int lane = tid & 31;
    const int wid = tid >> 5;
    const int wm = wid & 1;    // 2 row groups of 64
    const int wn = wid >> 1;   // 2 col groups of 64
    const int m0 = blockIdx.y * GTM;
    const int n0 = blockIdx.x * GTN;
    const int KT = K / GTK;
    const int g = lane >> 2;
    const int c2 = 2 * (lane & 3);

    const int a_row = lane & 15;
    const int a_ko  = (lane >> 4) * 8;
    const int b_row = ((lane >> 4) * 8) + (lane & 7);
    const int b_ko  = ((lane >> 3) & 1) * 8;

    auto fill = [&](int buf, int s) {
        __half* As = sh + buf * G_STG;
        __half* Bs = As + G_ASTG;
        const int k0 = s * GTK;
        #pragma unroll
        for (int j = 0; j < 8; j++) {
            int c = tid + j * 128;
            int row = c >> 3, ch = (c & 7) << 3;
            cp_async16(As + row * GLD + ch, A + (size_t)(m0 + row) * K + k0 + ch);
        }
        #pragma unroll
        for (int j = 0; j < 8; j++) {
            int c = tid + j * 128;
            int row = c >> 3, ch = (c & 7) << 3;
            cp_async16(Bs + row * GLD + ch, Bt + (size_t)(n0 + row) * K + k0 + ch);
        }
    };

    float acc[4][8][4];
    #pragma unroll
    for (int i = 0; i < 4; i++)
        #pragma unroll
        for (int j = 0; j < 8; j++)
            #pragma unroll
            for (int e = 0; e < 4; e++) acc[i][j][e] = 0.0f;

    fill(0, 0); cp_commit();
    fill(1, 1); cp_commit();

    for (int s = 0; s < KT; s++) {
        cp_wait<1>();
        __syncthreads();

        const __half* As = sh + (s & 1) * G_STG;
        const __half* Bs = As + G_ASTG;

        #pragma unroll
        for (int kk = 0; kk < 4; kk++) {
            uint32_t a[4][4];
            #pragma unroll
            for (int mt = 0; mt < 4; mt++)
                ldm_x4(a[mt][0], a[mt][1], a[mt][2], a[mt][3],
                       As + (wm * 64 + mt * 16 + a_row) * GLD + kk * 16 + a_ko);

            uint32_t bf[8][2];
            #pragma unroll
            for (int np = 0; np < 4; np++)
                ldm_x4(bf[2 * np][0], bf[2 * np][1], bf[2 * np + 1][0], bf[2 * np + 1][1],
                       Bs + (wn * 64 + np * 16 + b_row) * GLD + kk * 16 + b_ko);

            #pragma unroll
            for (int mt = 0; mt < 4; mt++)
                #pragma unroll
                for (int nt = 0; nt < 8; nt++)
                    mma_f16(acc[mt][nt], a[mt], bf[nt][0], bf[nt][1]);
        }

        __syncthreads();
        if (s + 2 < KT) fill(s & 1, s + 2);
        cp_commit();
    }

    #pragma unroll
    for (int mt = 0; mt < 4; mt++) {
        #pragma unroll
        for (int nt = 0; nt < 8; nt++) {
            const int row = m0 + wm * 64 + mt * 16 + g;
            const int col = n0 + wn * 64 + nt * 8 + c2;
            if (HALF_OUT) {
                __half* Ch = (__half*)Cout;
                *reinterpret_cast<__half2*>(Ch + (size_t)row * Ntot + col) =
                    __floats2half2_rn(acc[mt][nt][0], acc[mt][nt][1]);
                *reinterpret_cast<__half2*>(Ch + (size_t)(row + 8) * Ntot + col) =
                    __floats2half2_rn(acc[mt][nt][2], acc[mt][nt][3]);
            } else {
                float* Cf = (float*)Cout;
                *reinterpret_cast<float2*>(Cf + (size_t)row * Ntot + col) =
                    make_float2(acc[mt][nt][0], acc[mt][nt][1]);
                *reinterpret_cast<float2*>(Cf + (size_t)(row + 8) * Ntot + col) =
                    make_float2(acc[mt][nt][2], acc[mt][nt][3]);
            }
        }
    }
}

// ---------------- Flash attention: 128 q-rows, 4 warps x 32 rows ----------------
#define BQ 128
#define AT_LD 72
#define KV_TILE (64 * AT_LD)
#define AT_BUF (2 * KV_TILE)
#define AT_SMEM_HALVES (2 * AT_BUF + BQ * AT_LD)   // 27648
#define AT_SMEM_BYTES (AT_SMEM_HALVES * 2)         // 55296

__global__ void __launch_bounds__(128, 2) attn_kernel(
    const __half* __restrict__ qkvh, const __half* __restrict__ vT,
    __half* __restrict__ out)
{
    extern __shared__ __half smh[];
    const int tid = threadIdx.x;
    const int lane = tid & 31;
    const int w = tid >> 5;                      // warp owns q-rows [32w, 32w+32)
    const int g = lane >> 2;
    const int c2 = 2 * (lane & 3);
    const int qt = gridDim.x - 1 - blockIdx.x;   // heavy q-tiles first
    const int bh = blockIdx.y;
    const int b = bh >> 4;
    const int h = bh & 15;

    const int a_row = lane & 15;
    const int a_ko  = (lane >> 4) * 8;
    const int b_row = ((lane >> 4) * 8) + (lane & 7);
    const int b_ko  = ((lane >> 3) & 1) * 8;

    __half* Qs = smh + 2 * AT_BUF;
    const int NJ = 2 * qt + 2;

    auto fill = [&](int buf, int j) {
        __half* K = smh + buf * AT_BUF;
        __half* V = K + KV_TILE;
        const __half* kg = qkvh + (size_t)(b * SEQ + j * 64) * C3 + CH + h * 64;
        const __half* vg = vT + ((size_t)bh * 64) * SEQ + j * 64;
        #pragma unroll
        for (int i = 0; i < 4; i++) {
            int f = tid + i * 128;
            int r = f >> 3, ch = (f & 7) << 3;
            cp_async16(K + r * AT_LD + ch, kg + (size_t)r * C3 + ch);
            cp_async16(V + r * AT_LD + ch, vg + (size_t)r * SEQ + ch);
        }
    };

    fill(0, 0);
    cp_commit();

    {
        const __half* gq = qkvh + (size_t)(b * SEQ + qt * BQ) * C3 + h * 64;
        #pragma unroll
        for (int f = tid; f < 1024; f += 128) {
            int r = f >> 3, ch = (f & 7) << 3;
            *reinterpret_cast<uint4*>(Qs + r * AT_LD + ch) =
                *reinterpret_cast<const uint4*>(gq + (size_t)r * C3 + ch);
        }
    }
    __syncthreads();

    // Q a-fragments: 2 m-tiles x 4 k-steps (scaled by 1/8, exact)
    uint32_t aq[2][4][4];
    {
        const __half2 sc8 = __float2half2_rn(0.125f);
        #pragma unroll
        for (int mt = 0; mt < 2; mt++)
            #pragma unroll
            for (int kk = 0; kk < 4; kk++) {
                ldm_x4(aq[mt][kk][0], aq[mt][kk][1], aq[mt][kk][2], aq[mt][kk][3],
                       Qs + (w * 32 + mt * 16 + a_row) * AT_LD + kk * 16 + a_ko);
                #pragma unroll
                for (int e = 0; e < 4; e++) {
                    __half2 v = *reinterpret_cast<__half2*>(&aq[mt][kk][e]);
                    v = __hmul2(v, sc8);
                    aq[mt][kk][e] = *reinterpret_cast<uint32_t*>(&v);
                }
            }
    }

    float oc[2][8][4];
    #pragma unroll
    for (int mt = 0; mt < 2; mt++)
        #pragma unroll
        for (int t = 0; t < 8; t++)
            #pragma unroll
            for (int e = 0; e < 4; e++) oc[mt][t][e] = 0.0f;
    float mA[2] = {-INFINITY, -INFINITY}, mB[2] = {-INFINITY, -INFINITY};
    float lA[2] = {0.0f, 0.0f}, lB[2] = {0.0f, 0.0f};

    const int qrow0 = qt * BQ + w * 32;   // warp's first global q row

    for (int j = 0; j < NJ; j++) {
        cp_wait<0>();
        __syncthreads();
        if (j + 1 < NJ) { fill((j + 1) & 1, j + 1); cp_commit(); }

        const int jbase = j * 64;
        if (jbase > qrow0 + 31) continue;   // warp-uniform skip

        const __half* K = smh + (j & 1) * AT_BUF;
        const __half* V = K + KV_TILE;

        // ---- S = Q*K^T ----
        float sc[2][8][4];
        #pragma unroll
        for (int mt = 0; mt < 2; mt++)
            #pragma unroll
            for (int t = 0; t < 8; t++)
                #pragma unroll
                for (int e = 0; e < 4; e++) sc[mt][t][e] = 0.0f;

        #pragma unroll
        for (int kk = 0; kk < 4; kk++) {
            uint32_t kb[8][2];
            #pragma unroll
            for (int np = 0; np < 4; np++)
                ldm_x4(kb[2 * np][0], kb[2 * np][1], kb[2 * np + 1][0], kb[2 * np + 1][1],
                       K + (np * 16 + b_row) * AT_LD + kk * 16 + b_ko);
            #pragma unroll
            for (int mt = 0; mt < 2; mt++)
                #pragma unroll
                for (int nt = 0; nt < 8; nt++)
                    mma_f16(sc[mt][nt], aq[mt][kk], kb[nt][0], kb[nt][1]);
        }

        // ---- causal mask ----
        if (jbase + 63 > qrow0) {
            #pragma unroll
            for (int mt = 0; mt < 2; mt++) {
                const int qA = qrow0 + mt * 16 + g;
                #pragma unroll
                for (int t = 0; t < 8; t++) {
                    int cc0 = jbase + t * 8 + c2;
                    int cc1 = cc0 + 1;
                    if (cc0 > qA)     sc[mt][t][0] = -INFINITY;
                    if (cc1 > qA)     sc[mt][t][1] = -INFINITY;
                    if (cc0 > qA + 8) sc[mt][t][2] = -INFINITY;
                    if (cc1 > qA + 8) sc[mt][t][3] = -INFINITY;
                }
            }
        }

        // ---- online softmax (per m-tile) ----
        #pragma unroll
        for (int mt = 0; mt < 2; mt++) {
            float mxA = -INFINITY, mxB = -INFINITY;
            #pragma unroll
            for (int t = 0; t < 8; t++) {
                mxA = fmaxf(mxA, fmaxf(sc[mt][t][0], sc[mt][t][1]));
                mxB = fmaxf(mxB, fmaxf(sc[mt][t][2], sc[mt][t][3]));
            }
            #pragma unroll
            for (int o = 1; o <= 2; o <<= 1) {
                mxA = fmaxf(mxA, __shfl_xor_sync(0xffffffffu, mxA, o));
                mxB = fmaxf(mxB, __shfl_xor_sync(0xffffffffu, mxB, o));
            }
            const float mA2 = fmaxf(mA[mt], mxA);
            const float mB2 = fmaxf(mB[mt], mxB);
            const float alA = __expf(mA[mt] - mA2);
            const float alB = __expf(mB[mt] - mB2);

            float sA = 0.0f, sB = 0.0f;
            #pragma unroll
            for (int t = 0; t < 8; t++) {
                sc[mt][t][0] = __expf(sc[mt][t][0] - mA2);
                sc[mt][t][1] = __expf(sc[mt][t][1] - mA2);
                sc[mt][t][2] = __expf(sc[mt][t][2] - mB2);
                sc[mt][t][3] = __expf(sc[mt][t][3] - mB2);
                sA += sc[mt][t][0] + sc[mt][t][1];
                sB += sc[mt][t][2] + sc[mt][t][3];
            }
            #pragma unroll
            for (int o = 1; o <= 2; o <<= 1) {
                sA += __shfl_xor_sync(0xffffffffu, sA, o);
                sB += __shfl_xor_sync(0xffffffffu, sB, o);
            }
            mA[mt] = mA2; mB[mt] = mB2;
            lA[mt] = lA[mt] * alA + sA;
            lB[mt] = lB[mt] * alB + sB;

            #pragma unroll
            for (int t = 0; t < 8; t++) {
                oc[mt][t][0] *= alA; oc[mt][t][1] *= alA;
                oc[mt][t][2] *= alB; oc[mt][t][3] *= alB;
            }
        }

        // ---- O += P * V ----
        #pragma unroll
        for (int kk = 0; kk < 4; kk++) {
            uint32_t vb[8][2];
            #pragma unroll
            for (int np = 0; np < 4; np++)
                ldm_x4(vb[2 * np][0], vb[2 * np][1], vb[2 * np + 1][0], vb[2 * np + 1][1],
                       V + (np * 16 + b_row) * AT_LD + kk * 16 + b_ko);
            #pragma unroll
            for (int mt = 0; mt < 2; mt++) {
                uint32_t ap[4];
                ap[0] = pack_h2(sc[mt][2 * kk][0],     sc[mt][2 * kk][1]);
                ap[1] = pack_h2(sc[mt][2 * kk][2],     sc[mt][2 * kk][3]);
                ap[2] = pack_h2(sc[mt][2 * kk + 1][0], sc[mt][2 * kk + 1][1]);
                ap[3] = pack_h2(sc[mt][2 * kk + 1][2], sc[mt][2 * kk + 1][3]);
                #pragma unroll
                for (int nt = 0; nt < 8; nt++)
                    mma_f16(oc[mt][nt], ap, vb[nt][0], vb[nt][1]);
            }
        }
    }

    // ---- epilogue ----
    #pragma unroll
    for (int mt = 0; mt < 2; mt++) {
        const float iA = 1.0f / lA[mt];
        const float iB = 1.0f / lB[mt];
        __half* ob = out + (size_t)(b * SEQ + qt * BQ + w * 32 + mt * 16 + g) * CH + h * 64 + c2;
        #pragma unroll
        for (int t = 0; t < 8; t++) {
            *reinterpret_cast<__half2*>(ob + t * 8) =
                __floats2half2_rn(oc[mt][t][0] * iA, oc[mt][t][1] * iA);
            *reinterpret_cast<__half2*>(ob + 8 * CH + t * 8) =
                __floats2half2_rn(oc[mt][t][2] * iB, oc[mt][t][3] * iB);
        }
    }
}

// ---------------- launch ----------------
extern "C" void kernel_launch(void* const* d_in, const int* in_sizes, int n_in,
                              void* d_out, int out_size)
{
    const float* x     = (const float*)d_in[0];
    const float* w_qkv = (const float*)d_in[1];
    const float* w_out = (const float*)d_in[2];
    float* out = (float*)d_out;

    __half *qkvh, *attnh, *xh, *wqkvT, *woutT, *vT;
    cudaGetSymbolAddress((void**)&qkvh,  g_qkvh);
    cudaGetSymbolAddress((void**)&attnh, g_attnh);
    cudaGetSymbolAddress((void**)&xh,    g_xh);
    cudaGetSymbolAddress((void**)&wqkvT, g_wqkvT);
    cudaGetSymbolAddress((void**)&woutT, g_woutT);
    cudaGetSymbolAddress((void**)&vT,    g_vT);

    cudaFuncSetAttribute(gemm_f16_kernel<true>,  cudaFuncAttributeMaxDynamicSharedMemorySize, GEMM_SMEM);
    cudaFuncSetAttribute(gemm_f16_kernel<false>, cudaFuncAttributeMaxDynamicSharedMemorySize, GEMM_SMEM);
    cudaFuncSetAttribute(attn_kernel, cudaFuncAttributeMaxDynamicSharedMemorySize, AT_SMEM_BYTES);

    f2h_kernel<<<512, 256>>>((const float4*)x, (__half2*)xh, (ROWS * CH) / 4);
    {
        dim3 blk(32, 8);
        wtrans_kernel<<<dim3(C3 / 32, CH / 32), blk>>>(w_qkv, wqkvT, CH, C3);
        wtrans_kernel<<<dim3(CH / 32, CH / 32), blk>>>(w_out, woutT, CH, CH);
    }

    gemm_f16_kernel<true><<<dim3(C3 / GTN, ROWS / GTM), 128, GEMM_SMEM>>>(
        xh, wqkvT, qkvh, C3, CH);

    {
        dim3 blk(32, 8);
        vtrans_kernel<<<dim3(SEQ / 32, DK / 32, BATCH * NHEAD), blk>>>(qkvh, vT);
    }

    attn_kernel<<<dim3(SEQ / BQ, BATCH * NHEAD), 128, AT_SMEM_BYTES>>>(qkvh, vT, attnh);

    gemm_f16_kernel<false><<<dim3(CH / GTN, ROWS / GTM), 128, GEMM_SMEM>>>(
        attnh, woutT, out, CH, CH);
}

// round 9
// speedup vs baseline: 6.2531x; 1.0268x over previous
#include <cuda_runtime.h>
#include <cuda_fp16.h>
#include <math.h>
#include <stdint.h>

#define BATCH 4
#define SEQ   2048
#define CH    1024
#define NHEAD 16
#define DK    64
#define C3    3072
#define ROWS  (BATCH*SEQ)   // 8192

// ---------------- scratch ----------------
__device__ __align__(16) __half g_qkvh[(size_t)ROWS * C3];
__device__ __align__(16) __half g_attnh[(size_t)ROWS * CH];
__device__ __align__(16) __half g_xh[(size_t)ROWS * CH];
__device__ __align__(16) __half g_wqkvT[(size_t)C3 * CH];
__device__ __align__(16) __half g_woutT[(size_t)CH * CH];

// ---------------- helpers ----------------
__device__ __forceinline__ void cp_async16(void* smem_dst, const void* gmem_src) {
    unsigned s = (unsigned)__cvta_generic_to_shared(smem_dst);
    asm volatile("cp.async.cg.shared.global [%0], [%1], 16;\n" :: "r"(s), "l"(gmem_src));
}
__device__ __forceinline__ void cp_commit() {
    asm volatile("cp.async.commit_group;\n" ::);
}
template<int N>
__device__ __forceinline__ void cp_wait() {
    asm volatile("cp.async.wait_group %0;\n" :: "n"(N));
}
__device__ __forceinline__ void mma_f16(float c[4], const uint32_t a[4], uint32_t b0, uint32_t b1) {
    asm volatile(
        "mma.sync.aligned.m16n8k16.row.col.f32.f16.f16.f32 "
        "{%0,%1,%2,%3}, {%4,%5,%6,%7}, {%8,%9}, {%0,%1,%2,%3};"
        : "+f"(c[0]), "+f"(c[1]), "+f"(c[2]), "+f"(c[3])
        : "r"(a[0]), "r"(a[1]), "r"(a[2]), "r"(a[3]), "r"(b0), "r"(b1));
}
__device__ __forceinline__ uint32_t pack_h2(float x, float y) {
    __half2 h = __floats2half2_rn(x, y);
    return *reinterpret_cast<uint32_t*>(&h);
}
__device__ __forceinline__ void ldm_x4(uint32_t& r0, uint32_t& r1, uint32_t& r2, uint32_t& r3,
                                       const __half* p) {
    uint32_t addr = (uint32_t)__cvta_generic_to_shared(p);
    asm volatile("ldmatrix.sync.aligned.m8n8.x4.shared.b16 {%0,%1,%2,%3}, [%4];"
        : "=r"(r0), "=r"(r1), "=r"(r2), "=r"(r3) : "r"(addr));
}
__device__ __forceinline__ void ldm_x4_t(uint32_t& r0, uint32_t& r1, uint32_t& r2, uint32_t& r3,
                                         const __half* p) {
    uint32_t addr = (uint32_t)__cvta_generic_to_shared(p);
    asm volatile("ldmatrix.sync.aligned.m8n8.x4.trans.shared.b16 {%0,%1,%2,%3}, [%4];"
        : "=r"(r0), "=r"(r1), "=r"(r2), "=r"(r3) : "r"(addr));
}

// ---------------- pre-pass kernels ----------------
__global__ void f2h_kernel(const float4* __restrict__ in, __half2* __restrict__ out, int n4) {
    int i = blockIdx.x * blockDim.x + threadIdx.x;
    int stride = gridDim.x * blockDim.x;
    for (; i < n4; i += stride) {
        float4 v = in[i];
        out[2 * i]     = __floats2half2_rn(v.x, v.y);
        out[2 * i + 1] = __floats2half2_rn(v.z, v.w);
    }
}

__global__ void wtrans_kernel(const float* __restrict__ in, __half* __restrict__ out,
                              int R, int C) {
    __shared__ float t[32][33];
    int bx = blockIdx.x * 32;
    int by = blockIdx.y * 32;
    #pragma unroll
    for (int j = 0; j < 32; j += 8)
        t[threadIdx.y + j][threadIdx.x] = in[(size_t)(by + threadIdx.y + j) * C + bx + threadIdx.x];
    __syncthreads();
    #pragma unroll
    for (int j = 0; j < 32; j += 8)
        out[(size_t)(bx + threadIdx.y + j) * R + by + threadIdx.x] =
            __float2half(t[threadIdx.x][threadIdx.y + j]);
}

// ---------------- fp16 GEMM: C[M,N] = A[M,K] @ Bt[N,K]^T ----------------
// CTA 128x128, 4 warps of 64x64, TK=32, 4-stage cp.async, ONE barrier/stage.
#define GTM 128
#define GTN 128
#define GTK 32
#define GLD 40
#define G_ASTG (GTM * GLD)            // 5120 halves
#define G_STG  (2 * G_ASTG)           // 10240 halves per stage
#define GEMM_SMEM (4 * G_STG * 2)     // 81920 bytes

template<bool HALF_OUT>
__global__ void __launch_bounds__(128, 2) gemm_f16_kernel(
    const __half* __restrict__ A, const __half* __restrict__ Bt,
    void* __restrict__ Cout, int Ntot, int K)
{
    extern __shared__ __half sh[];
    const int tid = threadIdx.x;
    const int lane = tid & 31;
    const int wid = tid >> 5;
    const int wm = wid & 1;
    const int wn = wid >> 1;
    const int m0 = blockIdx.y * GTM;
    const int n0 = blockIdx.x * GTN;
    const int KT = K / GTK;   // 32
    const int g = lane >> 2;
    const int c2 = 2 * (lane & 3);

    const int a_row = lane & 15;
    const int a_ko  = (lane >> 4) * 8;
    const int b_row = ((lane >> 4) * 8) + (lane & 7);
    const int b_ko  = ((lane >> 3) & 1) * 8;

    auto fill = [&](int buf, int s) {
        __half* As = sh + buf * G_STG;
        __half* Bs = As + G_ASTG;
        const int k0 = s * GTK;
        #pragma unroll
        for (int j = 0; j < 4; j++) {
            int c = tid + j * 128;
            int row = c >> 2, ch = (c & 3) << 3;
            cp_async16(As + row * GLD + ch, A + (size_t)(m0 + row) * K + k0 + ch);
        }
        #pragma unroll
        for (int j = 0; j < 4; j++) {
            int c = tid + j * 128;
            int row = c >> 2, ch = (c & 3) << 3;
            cp_async16(Bs + row * GLD + ch, Bt + (size_t)(n0 + row) * K + k0 + ch);
        }
    };

    float acc[4][8][4];
    #pragma unroll
    for (int i = 0; i < 4; i++)
        #pragma unroll
        for (int j = 0; j < 8; j++)
            #pragma unroll
            for (int e = 0; e < 4; e++) acc[i][j][e] = 0.0f;

    fill(0, 0); cp_commit();
    fill(1, 1); cp_commit();
    fill(2, 2); cp_commit();

    for (int s = 0; s < KT; s++) {
        cp_wait<2>();
        __syncthreads();
        if (s + 3 < KT) fill((s + 3) & 3, s + 3);
        cp_commit();

        const __half* As = sh + (s & 3) * G_STG;
        const __half* Bs = As + G_ASTG;

        #pragma unroll
        for (int kk = 0; kk < 2; kk++) {
            uint32_t a[4][4];
            #pragma unroll
            for (int mt = 0; mt < 4; mt++)
                ldm_x4(a[mt][0], a[mt][1], a[mt][2], a[mt][3],
                       As + (wm * 64 + mt * 16 + a_row) * GLD + kk * 16 + a_ko);

            uint32_t bf[8][2];
            #pragma unroll
            for (int np = 0; np < 4; np++)
                ldm_x4(bf[2 * np][0], bf[2 * np][1], bf[2 * np + 1][0], bf[2 * np + 1][1],
                       Bs + (wn * 64 + np * 16 + b_row) * GLD + kk * 16 + b_ko);

            #pragma unroll
            for (int mt = 0; mt < 4; mt++)
                #pragma unroll
                for (int nt = 0; nt < 8; nt++)
                    mma_f16(acc[mt][nt], a[mt], bf[nt][0], bf[nt][1]);
        }
    }

    #pragma unroll
    for (int mt = 0; mt < 4; mt++) {
        #pragma unroll
        for (int nt = 0; nt < 8; nt++) {
            const int row = m0 + wm * 64 + mt * 16 + g;
            const int col = n0 + wn * 64 + nt * 8 + c2;
            if (HALF_OUT) {
                __half* Ch = (__half*)Cout;
                *reinterpret_cast<__half2*>(Ch + (size_t)row * Ntot + col) =
                    __floats2half2_rn(acc[mt][nt][0], acc[mt][nt][1]);
                *reinterpret_cast<__half2*>(Ch + (size_t)(row + 8) * Ntot + col) =
                    __floats2half2_rn(acc[mt][nt][2], acc[mt][nt][3]);
            } else {
                float* Cf = (float*)Cout;
                *reinterpret_cast<float2*>(Cf + (size_t)row * Ntot + col) =
                    make_float2(acc[mt][nt][0], acc[mt][nt][1]);
                *reinterpret_cast<float2*>(Cf + (size_t)(row + 8) * Ntot + col) =
                    make_float2(acc[mt][nt][2], acc[mt][nt][3]);
            }
        }
    }
}

// ---------------- Flash attention: 128 q-rows, 4 warps x 32 rows ----------------
// V loaded directly from qkvh; PV B-fragments via ldmatrix.trans. 3-stage K/V pipeline.
#define BQ 128
#define AT_LD 72
#define KV_TILE (64 * AT_LD)
#define AT_BUF (2 * KV_TILE)                        // K+V per stage = 9216 halves
#define AT_SMEM_HALVES (3 * AT_BUF + BQ * AT_LD)    // 36864
#define AT_SMEM_BYTES (AT_SMEM_HALVES * 2)          // 73728

__global__ void __launch_bounds__(128, 2) attn_kernel(
    const __half* __restrict__ qkvh, __half* __restrict__ out)
{
    extern __shared__ __half smh[];
    const int tid = threadIdx.x;
    const int lane = tid & 31;
    const int w = tid >> 5;
    const int g = lane >> 2;
    const int c2 = 2 * (lane & 3);
    const int qt = gridDim.x - 1 - blockIdx.x;
    const int bh = blockIdx.y;
    const int b = bh >> 4;
    const int h = bh & 15;

    const int a_row = lane & 15;
    const int a_ko  = (lane >> 4) * 8;
    const int b_row = ((lane >> 4) * 8) + (lane & 7);
    const int b_ko  = ((lane >> 3) & 1) * 8;
    // ldmatrix.trans lane addressing for V (row-major [t][d] -> B-frags of V^T)
    const int vt_row = ((lane >> 3) & 1) * 8 + (lane & 7);   // k(t) index within 16
    const int vt_co  = (lane >> 4) * 8;                      // n(d) offset 0/8

    __half* Qs = smh + 3 * AT_BUF;
    const int NJ = 2 * qt + 2;

    auto fill = [&](int buf, int j) {
        __half* K = smh + buf * AT_BUF;
        __half* V = K + KV_TILE;
        const __half* kg = qkvh + (size_t)(b * SEQ + j * 64) * C3 + CH + h * 64;
        #pragma unroll
        for (int i = 0; i < 4; i++) {
            int f = tid + i * 128;
            int r = f >> 3, ch = (f & 7) << 3;
            const __half* src = kg + (size_t)r * C3 + ch;
            cp_async16(K + r * AT_LD + ch, src);
            cp_async16(V + r * AT_LD + ch, src + CH);
        }
    };

    fill(0, 0); cp_commit();
    if (NJ > 1) fill(1, 1);
    cp_commit();

    {
        const __half* gq = qkvh + (size_t)(b * SEQ + qt * BQ) * C3 + h * 64;
        #pragma unroll
        for (int f = tid; f < 1024; f += 128) {
            int r = f >> 3, ch = (f & 7) << 3;
            *reinterpret_cast<uint4*>(Qs + r * AT_LD + ch) =
                *reinterpret_cast<const uint4*>(gq + (size_t)r * C3 + ch);
        }
    }
    __syncthreads();

    uint32_t aq[2][4][4];
    {
        const __half2 sc8 = __float2half2_rn(0.125f);
        #pragma unroll
        for (int mt = 0; mt < 2; mt++)
            #pragma unroll
            for (int kk = 0; kk < 4; kk++) {
                ldm_x4(aq[mt][kk][0], aq[mt][kk][1], aq[mt][kk][2], aq[mt][kk][3],
                       Qs + (w * 32 + mt * 16 + a_row) * AT_LD + kk * 16 + a_ko);
                #pragma unroll
                for (int e = 0; e < 4; e++) {
                    __half2 v = *reinterpret_cast<__half2*>(&aq[mt][kk][e]);
                    v = __hmul2(v, sc8);
                    aq[mt][kk][e] = *reinterpret_cast<uint32_t*>(&v);
                }
            }
    }

    float oc[2][8][4];
    #pragma unroll
    for (int mt = 0; mt < 2; mt++)
        #pragma unroll
        for (int t = 0; t < 8; t++)
            #pragma unroll
            for (int e = 0; e < 4; e++) oc[mt][t][e] = 0.0f;
    float mA[2] = {-INFINITY, -INFINITY}, mB[2] = {-INFINITY, -INFINITY};
    float lA[2] = {0.0f, 0.0f}, lB[2] = {0.0f, 0.0f};

    const int qrow0 = qt * BQ + w * 32;

    int buf = 0;
    for (int j = 0; j < NJ; j++) {
        cp_wait<1>();
        __syncthreads();
        if (j + 2 < NJ) fill((buf + 2 >= 3) ? buf - 1 : buf + 2, j + 2);
        cp_commit();

        const int jbase = j * 64;
        const __half* K = smh + buf * AT_BUF;
        const __half* V = K + KV_TILE;
        buf = (buf == 2) ? 0 : buf + 1;

        if (jbase > qrow0 + 31) continue;   // warp-uniform skip

        // ---- S = Q*K^T ----
        float sc[2][8][4];
        #pragma unroll
        for (int mt = 0; mt < 2; mt++)
            #pragma unroll
            for (int t = 0; t < 8; t++)
                #pragma unroll
                for (int e = 0; e < 4; e++) sc[mt][t][e] = 0.0f;

        #pragma unroll
        for (int kk = 0; kk < 4; kk++) {
            uint32_t kb[8][2];
            #pragma unroll
            for (int np = 0; np < 4; np++)
                ldm_x4(kb[2 * np][0], kb[2 * np][1], kb[2 * np + 1][0], kb[2 * np + 1][1],
                       K + (np * 16 + b_row) * AT_LD + kk * 16 + b_ko);
            #pragma unroll
            for (int mt = 0; mt < 2; mt++)
                #pragma unroll
                for (int nt = 0; nt < 8; nt++)
                    mma_f16(sc[mt][nt], aq[mt][kk], kb[nt][0], kb[nt][1]);
        }

        // ---- causal mask ----
        if (jbase + 63 > qrow0) {
            #pragma unroll
            for (int mt = 0; mt < 2; mt++) {
                const int qA = qrow0 + mt * 16 + g;
                #pragma unroll
                for (int t = 0; t < 8; t++) {
                    int cc0 = jbase + t * 8 + c2;
                    int cc1 = cc0 + 1;
                    if (cc0 > qA)     sc[mt][t][0] = -INFINITY;
                    if (cc1 > qA)     sc[mt][t][1] = -INFINITY;
                    if (cc0 > qA + 8) sc[mt][t][2] = -INFINITY;
                    if (cc1 > qA + 8) sc[mt][t][3] = -INFINITY;
                }
            }
        }

        // ---- online softmax ----
        #pragma unroll
        for (int mt = 0; mt < 2; mt++) {
            float mxA = -INFINITY, mxB = -INFINITY;
            #pragma unroll
            for (int t = 0; t < 8; t++) {
                mxA = fmaxf(mxA, fmaxf(sc[mt][t][0], sc[mt][t][1]));
                mxB = fmaxf(mxB, fmaxf(sc[mt][t][2], sc[mt][t][3]));
            }
            #pragma unroll
            for (int o = 1; o <= 2; o <<= 1) {
                mxA = fmaxf(mxA, __shfl_xor_sync(0xffffffffu, mxA, o));
                mxB = fmaxf(mxB, __shfl_xor_sync(0xffffffffu, mxB, o));
            }
            const float mA2 = fmaxf(mA[mt], mxA);
            const float mB2 = fmaxf(mB[mt], mxB);
            const float alA = __expf(mA[mt] - mA2);
            const float alB = __expf(mB[mt] - mB2);

            float sA = 0.0f, sB = 0.0f;
            #pragma unroll
            for (int t = 0; t < 8; t++) {
                sc[mt][t][0] = __expf(sc[mt][t][0] - mA2);
                sc[mt][t][1] = __expf(sc[mt][t][1] - mA2);
                sc[mt][t][2] = __expf(sc[mt][t][2] - mB2);
                sc[mt][t][3] = __expf(sc[mt][t][3] - mB2);
                sA += sc[mt][t][0] + sc[mt][t][1];
                sB += sc[mt][t][2] + sc[mt][t][3];
            }
            #pragma unroll
            for (int o = 1; o <= 2; o <<= 1) {
                sA += __shfl_xor_sync(0xffffffffu, sA, o);
                sB += __shfl_xor_sync(0xffffffffu, sB, o);
            }
            mA[mt] = mA2; mB[mt] = mB2;
            lA[mt] = lA[mt] * alA + sA;
            lB[mt] = lB[mt] * alB + sB;

            #pragma unroll
            for (int t = 0; t < 8; t++) {
                oc[mt][t][0] *= alA; oc[mt][t][1] *= alA;
                oc[mt][t][2] *= alB; oc[mt][t][3] *= alB;
            }
        }

        // ---- O += P * V (V via ldmatrix.trans from row-major [t][d]) ----
        #pragma unroll
        for (int kk = 0; kk < 4; kk++) {
            uint32_t vb[8][2];
            #pragma unroll
            for (int np = 0; np < 4; np++)
                ldm_x4_t(vb[2 * np][0], vb[2 * np][1], vb[2 * np + 1][0], vb[2 * np + 1][1],
                         V + (kk * 16 + vt_row) * AT_LD + np * 16 + vt_co);
            #pragma unroll
            for (int mt = 0; mt < 2; mt++) {
                uint32_t ap[4];
                ap[0] = pack_h2(sc[mt][2 * kk][0],     sc[mt][2 * kk][1]);
                ap[1] = pack_h2(sc[mt][2 * kk][2],     sc[mt][2 * kk][3]);
                ap[2] = pack_h2(sc[mt][2 * kk + 1][0], sc[mt][2 * kk + 1][1]);
                ap[3] = pack_h2(sc[mt][2 * kk + 1][2], sc[mt][2 * kk + 1][3]);
                #pragma unroll
                for (int nt = 0; nt < 8; nt++)
                    mma_f16(oc[mt][nt], ap, vb[nt][0], vb[nt][1]);
            }
        }
    }

    // ---- epilogue ----
    #pragma unroll
    for (int mt = 0; mt < 2; mt++) {
        const float iA = 1.0f / lA[mt];
        const float iB = 1.0f / lB[mt];
        __half* ob = out + (size_t)(b * SEQ + qt * BQ + w * 32 + mt * 16 + g) * CH + h * 64 + c2;
        #pragma unroll
        for (int t = 0; t < 8; t++) {
            *reinterpret_cast<__half2*>(ob + t * 8) =
                __floats2half2_rn(oc[mt][t][0] * iA, oc[mt][t][1] * iA);
            *reinterpret_cast<__half2*>(ob + 8 * CH + t * 8) =
                __floats2half2_rn(oc[mt][t][2] * iB, oc[mt][t][3] * iB);
        }
    }
}

// ---------------- launch ----------------
extern "C" void kernel_launch(void* const* d_in, const int* in_sizes, int n_in,
                              void* d_out, int out_size)
{
    const float* x     = (const float*)d_in[0];
    const float* w_qkv = (const float*)d_in[1];
    const float* w_out = (const float*)d_in[2];
    float* out = (float*)d_out;

    __half *qkvh, *attnh, *xh, *wqkvT, *woutT;
    cudaGetSymbolAddress((void**)&qkvh,  g_qkvh);
    cudaGetSymbolAddress((void**)&attnh, g_attnh);
    cudaGetSymbolAddress((void**)&xh,    g_xh);
    cudaGetSymbolAddress((void**)&wqkvT, g_wqkvT);
    cudaGetSymbolAddress((void**)&woutT, g_woutT);

    cudaFuncSetAttribute(gemm_f16_kernel<true>,  cudaFuncAttributeMaxDynamicSharedMemorySize, GEMM_SMEM);
    cudaFuncSetAttribute(gemm_f16_kernel<false>, cudaFuncAttributeMaxDynamicSharedMemorySize, GEMM_SMEM);
    cudaFuncSetAttribute(attn_kernel, cudaFuncAttributeMaxDynamicSharedMemorySize, AT_SMEM_BYTES);

    f2h_kernel<<<512, 256>>>((const float4*)x, (__half2*)xh, (ROWS * CH) / 4);
    {
        dim3 blk(32, 8);
        wtrans_kernel<<<dim3(C3 / 32, CH / 32), blk>>>(w_qkv, wqkvT, CH, C3);
        wtrans_kernel<<<dim3(CH / 32, CH / 32), blk>>>(w_out, woutT, CH, CH);
    }

    gemm_f16_kernel<true><<<dim3(C3 / GTN, ROWS / GTM), 128, GEMM_SMEM>>>(
        xh, wqkvT, qkvh, C3, CH);

    attn_kernel<<<dim3(SEQ / BQ, BATCH * NHEAD), 128, AT_SMEM_BYTES>>>(qkvh, attnh);

    gemm_f16_kernel<false><<<dim3(CH / GTN, ROWS / GTM), 128, GEMM_SMEM>>>(
        attnh, woutT, out, CH, CH);
}

// round 10
// speedup vs baseline: 6.2727x; 1.0031x over previous
#include <cuda_runtime.h>
#include <cuda_fp16.h>
#include <math.h>
#include <stdint.h>

#define BATCH 4
#define SEQ   2048
#define CH    1024
#define NHEAD 16
#define DK    64
#define C3    3072
#define ROWS  (BATCH*SEQ)   // 8192

// ---------------- scratch ----------------
__device__ __align__(16) __half g_qkvh[(size_t)ROWS * C3];
__device__ __align__(16) __half g_attnh[(size_t)ROWS * CH];
__device__ __align__(16) __half g_xh[(size_t)ROWS * CH];
__device__ __align__(16) __half g_wqkvh[(size_t)CH * C3];   // [K,N] natural layout
__device__ __align__(16) __half g_wouth[(size_t)CH * CH];   // [K,N] natural layout

// ---------------- helpers ----------------
__device__ __forceinline__ void cp_async16(void* smem_dst, const void* gmem_src) {
    unsigned s = (unsigned)__cvta_generic_to_shared(smem_dst);
    asm volatile("cp.async.cg.shared.global [%0], [%1], 16;\n" :: "r"(s), "l"(gmem_src));
}
__device__ __forceinline__ void cp_commit() {
    asm volatile("cp.async.commit_group;\n" ::);
}
template<int N>
__device__ __forceinline__ void cp_wait() {
    asm volatile("cp.async.wait_group %0;\n" :: "n"(N));
}
__device__ __forceinline__ void mma_f16(float c[4], const uint32_t a[4], uint32_t b0, uint32_t b1) {
    asm volatile(
        "mma.sync.aligned.m16n8k16.row.col.f32.f16.f16.f32 "
        "{%0,%1,%2,%3}, {%4,%5,%6,%7}, {%8,%9}, {%0,%1,%2,%3};"
        : "+f"(c[0]), "+f"(c[1]), "+f"(c[2]), "+f"(c[3])
        : "r"(a[0]), "r"(a[1]), "r"(a[2]), "r"(a[3]), "r"(b0), "r"(b1));
}
__device__ __forceinline__ uint32_t pack_h2(float x, float y) {
    __half2 h = __floats2half2_rn(x, y);
    return *reinterpret_cast<uint32_t*>(&h);
}
__device__ __forceinline__ void ldm_x4(uint32_t& r0, uint32_t& r1, uint32_t& r2, uint32_t& r3,
                                       const __half* p) {
    uint32_t addr = (uint32_t)__cvta_generic_to_shared(p);
    asm volatile("ldmatrix.sync.aligned.m8n8.x4.shared.b16 {%0,%1,%2,%3}, [%4];"
        : "=r"(r0), "=r"(r1), "=r"(r2), "=r"(r3) : "r"(addr));
}
__device__ __forceinline__ void ldm_x4_t(uint32_t& r0, uint32_t& r1, uint32_t& r2, uint32_t& r3,
                                         const __half* p) {
    uint32_t addr = (uint32_t)__cvta_generic_to_shared(p);
    asm volatile("ldmatrix.sync.aligned.m8n8.x4.trans.shared.b16 {%0,%1,%2,%3}, [%4];"
        : "=r"(r0), "=r"(r1), "=r"(r2), "=r"(r3) : "r"(addr));
}

// ---------------- fused pre-pass: fp32 -> fp16 for x, w_qkv, w_out ----------------
__global__ void f2h3_kernel(const float4* __restrict__ a, __half2* __restrict__ ah, int na,
                            const float4* __restrict__ b, __half2* __restrict__ bh, int nb,
                            const float4* __restrict__ c, __half2* __restrict__ ch, int nc)
{
    int i = blockIdx.x * blockDim.x + threadIdx.x;
    const int stride = gridDim.x * blockDim.x;
    const int tot = na + nb + nc;
    for (; i < tot; i += stride) {
        const float4* src;
        __half2* dst;
        int k;
        if (i < na)            { src = a; dst = ah; k = i; }
        else if (i < na + nb)  { src = b; dst = bh; k = i - na; }
        else                   { src = c; dst = ch; k = i - na - nb; }
        float4 v = src[k];
        dst[2 * k]     = __floats2half2_rn(v.x, v.y);
        dst[2 * k + 1] = __floats2half2_rn(v.z, v.w);
    }
}

// ---------------- fp16 GEMM: C[M,N] = A[M,K] @ B[K,N] ----------------
// CTA 128xTN, 4 warps of 64x(TN/2), TK=32, 4-stage cp.async, one barrier/stage.
// B kept in natural [K,N] layout; B-fragments via ldmatrix.trans (V-pattern from attention).
#define GTK 32
#define GALD 40
#define G_ASTG (128 * GALD)           // 5120 halves

template<bool HALF_OUT, int TN>
__global__ void __launch_bounds__(128, 2) gemm_f16_kernel(
    const __half* __restrict__ A, const __half* __restrict__ B,
    void* __restrict__ Cout, int Ntot, int K)
{
    constexpr int WN   = TN / 2;       // warp col extent
    constexpr int NT   = WN / 8;       // n-tiles per warp
    constexpr int NG   = WN / 16;      // ldmatrix groups per warp
    constexpr int BLD  = TN + 8;       // B smem row stride (halves)
    constexpr int BSTG = GTK * BLD;
    constexpr int STG  = G_ASTG + BSTG;

    extern __shared__ __half sh[];
    const int tid = threadIdx.x;
    const int lane = tid & 31;
    const int wid = tid >> 5;
    const int wm = wid & 1;
    const int wn = wid >> 1;
    const int m0 = blockIdx.y * 128;
    const int n0 = blockIdx.x * TN;
    const int KT = K / GTK;
    const int g = lane >> 2;
    const int c2 = 2 * (lane & 3);

    const int a_row = lane & 15;
    const int a_ko  = (lane >> 4) * 8;
    // trans-B lane addressing (identical to attention V pattern)
    const int vt_row = ((lane >> 3) & 1) * 8 + (lane & 7);
    const int vt_co  = (lane >> 4) * 8;

    auto fill = [&](int buf, int s) {
        __half* As = sh + buf * STG;
        __half* Bs = As + G_ASTG;
        const int k0 = s * GTK;
        #pragma unroll
        for (int j = 0; j < 4; j++) {   // A: 128x32 = 512 chunks
            int c = tid + j * 128;
            int row = c >> 2, chh = (c & 3) << 3;
            cp_async16(As + row * GALD + chh, A + (size_t)(m0 + row) * K + k0 + chh);
        }
        #pragma unroll
        for (int j = 0; j < TN / 32; j++) {  // B: 32xTN halves = 32*TN/8 chunks
            int c = tid + j * 128;
            int row = c / (TN / 8);
            int chh = (c % (TN / 8)) * 8;
            cp_async16(Bs + row * BLD + chh, B + (size_t)(k0 + row) * Ntot + n0 + chh);
        }
    };

    float acc[4][NT][4];
    #pragma unroll
    for (int i = 0; i < 4; i++)
        #pragma unroll
        for (int j = 0; j < NT; j++)
            #pragma unroll
            for (int e = 0; e < 4; e++) acc[i][j][e] = 0.0f;

    fill(0, 0); cp_commit();
    fill(1, 1); cp_commit();
    fill(2, 2); cp_commit();

    for (int s = 0; s < KT; s++) {
        cp_wait<2>();
        __syncthreads();
        if (s + 3 < KT) fill((s + 3) & 3, s + 3);
        cp_commit();

        const __half* As = sh + (s & 3) * STG;
        const __half* Bs = As + G_ASTG;

        #pragma unroll
        for (int kk = 0; kk < 2; kk++) {
            uint32_t a[4][4];
            #pragma unroll
            for (int mt = 0; mt < 4; mt++)
                ldm_x4(a[mt][0], a[mt][1], a[mt][2], a[mt][3],
                       As + (wm * 64 + mt * 16 + a_row) * GALD + kk * 16 + a_ko);

            uint32_t bf[NT][2];
            #pragma unroll
            for (int ng = 0; ng < NG; ng++)
                ldm_x4_t(bf[2 * ng][0], bf[2 * ng][1], bf[2 * ng + 1][0], bf[2 * ng + 1][1],
                         Bs + (kk * 16 + vt_row) * BLD + wn * WN + ng * 16 + vt_co);

            #pragma unroll
            for (int mt = 0; mt < 4; mt++)
                #pragma unroll
                for (int nt = 0; nt < NT; nt++)
                    mma_f16(acc[mt][nt], a[mt], bf[nt][0], bf[nt][1]);
        }
    }

    #pragma unroll
    for (int mt = 0; mt < 4; mt++) {
        #pragma unroll
        for (int nt = 0; nt < NT; nt++) {
            const int row = m0 + wm * 64 + mt * 16 + g;
            const int col = n0 + wn * WN + nt * 8 + c2;
            if (HALF_OUT) {
                __half* Ch = (__half*)Cout;
                *reinterpret_cast<__half2*>(Ch + (size_t)row * Ntot + col) =
                    __floats2half2_rn(acc[mt][nt][0], acc[mt][nt][1]);
                *reinterpret_cast<__half2*>(Ch + (size_t)(row + 8) * Ntot + col) =
                    __floats2half2_rn(acc[mt][nt][2], acc[mt][nt][3]);
            } else {
                float* Cf = (float*)Cout;
                *reinterpret_cast<float2*>(Cf + (size_t)row * Ntot + col) =
                    make_float2(acc[mt][nt][0], acc[mt][nt][1]);
                *reinterpret_cast<float2*>(Cf + (size_t)(row + 8) * Ntot + col) =
                    make_float2(acc[mt][nt][2], acc[mt][nt][3]);
            }
        }
    }
}

#define GEMM_SMEM_128 ((G_ASTG + GTK * 136) * 2 * 4)   // 75776 bytes
#define GEMM_SMEM_64  ((G_ASTG + GTK * 72)  * 2 * 4)   // 59392 bytes

// ---------------- Flash attention: 128 q-rows, 4 warps x 32 rows (R9, unchanged) ----------------
#define BQ 128
#define AT_LD 72
#define KV_TILE (64 * AT_LD)
#define AT_BUF (2 * KV_TILE)
#define AT_SMEM_HALVES (3 * AT_BUF + BQ * AT_LD)
#define AT_SMEM_BYTES (AT_SMEM_HALVES * 2)          // 73728

__global__ void __launch_bounds__(128, 2) attn_kernel(
    const __half* __restrict__ qkvh, __half* __restrict__ out)
{
    extern __shared__ __half smh[];
    const int tid = threadIdx.x;
    const int lane = tid & 31;
    const int w = tid >> 5;
    const int g = lane >> 2;
    const int c2 = 2 * (lane & 3);
    const int qt = gridDim.x - 1 - blockIdx.x;
    const int bh = blockIdx.y;
    const int b = bh >> 4;
    const int h = bh & 15;

    const int a_row = lane & 15;
    const int a_ko  = (lane >> 4) * 8;
    const int b_row = ((lane >> 4) * 8) + (lane & 7);
    const int b_ko  = ((lane >> 3) & 1) * 8;
    const int vt_row = ((lane >> 3) & 1) * 8 + (lane & 7);
    const int vt_co  = (lane >> 4) * 8;

    __half* Qs = smh + 3 * AT_BUF;
    const int NJ = 2 * qt + 2;

    auto fill = [&](int buf, int j) {
        __half* K = smh + buf * AT_BUF;
        __half* V = K + KV_TILE;
        const __half* kg = qkvh + (size_t)(b * SEQ + j * 64) * C3 + CH + h * 64;
        #pragma unroll
        for (int i = 0; i < 4; i++) {
            int f = tid + i * 128;
            int r = f >> 3, ch = (f & 7) << 3;
            const __half* src = kg + (size_t)r * C3 + ch;
            cp_async16(K + r * AT_LD + ch, src);
            cp_async16(V + r * AT_LD + ch, src + CH);
        }
    };

    fill(0, 0); cp_commit();
    if (NJ > 1) fill(1, 1);
    cp_commit();

    {
        const __half* gq = qkvh + (size_t)(b * SEQ + qt * BQ) * C3 + h * 64;
        #pragma unroll
        for (int f = tid; f < 1024; f += 128) {
            int r = f >> 3, ch = (f & 7) << 3;
            *reinterpret_cast<uint4*>(Qs + r * AT_LD + ch) =
                *reinterpret_cast<const uint4*>(gq + (size_t)r * C3 + ch);
        }
    }
    __syncthreads();

    uint32_t aq[2][4][4];
    {
        const __half2 sc8 = __float2half2_rn(0.125f);
        #pragma unroll
        for (int mt = 0; mt < 2; mt++)
            #pragma unroll
            for (int kk = 0; kk < 4; kk++) {
                ldm_x4(aq[mt][kk][0], aq[mt][kk][1], aq[mt][kk][2], aq[mt][kk][3],
                       Qs + (w * 32 + mt * 16 + a_row) * AT_LD + kk * 16 + a_ko);
                #pragma unroll
                for (int e = 0; e < 4; e++) {
                    __half2 v = *reinterpret_cast<__half2*>(&aq[mt][kk][e]);
                    v = __hmul2(v, sc8);
                    aq[mt][kk][e] = *reinterpret_cast<uint32_t*>(&v);
                }
            }
    }

    float oc[2][8][4];
    #pragma unroll
    for (int mt = 0; mt < 2; mt++)
        #pragma unroll
        for (int t = 0; t < 8; t++)
            #pragma unroll
            for (int e = 0; e < 4; e++) oc[mt][t][e] = 0.0f;
    float mA[2] = {-INFINITY, -INFINITY}, mB[2] = {-INFINITY, -INFINITY};
    float lA[2] = {0.0f, 0.0f}, lB[2] = {0.0f, 0.0f};

    const int qrow0 = qt * BQ + w * 32;

    int buf = 0;
    for (int j = 0; j < NJ; j++) {
        cp_wait<1>();
        __syncthreads();
        if (j + 2 < NJ) fill((buf + 2 >= 3) ? buf - 1 : buf + 2, j + 2);
        cp_commit();

        const int jbase = j * 64;
        const __half* K = smh + buf * AT_BUF;
        const __half* V = K + KV_TILE;
        buf = (buf == 2) ? 0 : buf + 1;

        if (jbase > qrow0 + 31) continue;

        float sc[2][8][4];
        #pragma unroll
        for (int mt = 0; mt < 2; mt++)
            #pragma unroll
            for (int t = 0; t < 8; t++)
                #pragma unroll
                for (int e = 0; e < 4; e++) sc[mt][t][e] = 0.0f;

        #pragma unroll
        for (int kk = 0; kk < 4; kk++) {
            uint32_t kb[8][2];
            #pragma unroll
            for (int np = 0; np < 4; np++)
                ldm_x4(kb[2 * np][0], kb[2 * np][1], kb[2 * np + 1][0], kb[2 * np + 1][1],
                       K + (np * 16 + b_row) * AT_LD + kk * 16 + b_ko);
            #pragma unroll
            for (int mt = 0; mt < 2; mt++)
                #pragma unroll
                for (int nt = 0; nt < 8; nt++)
                    mma_f16(sc[mt][nt], aq[mt][kk], kb[nt][0], kb[nt][1]);
        }

        if (jbase + 63 > qrow0) {
            #pragma unroll
            for (int mt = 0; mt < 2; mt++) {
                const int qA = qrow0 + mt * 16 + g;
                #pragma unroll
                for (int t = 0; t < 8; t++) {
                    int cc0 = jbase + t * 8 + c2;
                    int cc1 = cc0 + 1;
                    if (cc0 > qA)     sc[mt][t][0] = -INFINITY;
                    if (cc1 > qA)     sc[mt][t][1] = -INFINITY;
                    if (cc0 > qA + 8) sc[mt][t][2] = -INFINITY;
                    if (cc1 > qA + 8) sc[mt][t][3] = -INFINITY;
                }
            }
        }

        #pragma unroll
        for (int mt = 0; mt < 2; mt++) {
            float mxA = -INFINITY, mxB = -INFINITY;
            #pragma unroll
            for (int t = 0; t < 8; t++) {
                mxA = fmaxf(mxA, fmaxf(sc[mt][t][0], sc[mt][t][1]));
                mxB = fmaxf(mxB, fmaxf(sc[mt][t][2], sc[mt][t][3]));
            }
            #pragma unroll
            for (int o = 1; o <= 2; o <<= 1) {
                mxA = fmaxf(mxA, __shfl_xor_sync(0xffffffffu, mxA, o));
                mxB = fmaxf(mxB, __shfl_xor_sync(0xffffffffu, mxB, o));
            }
            const float mA2 = fmaxf(mA[mt], mxA);
            const float mB2 = fmaxf(mB[mt], mxB);
            const float alA = __expf(mA[mt] - mA2);
            const float alB = __expf(mB[mt] - mB2);

            float sA = 0.0f, sB = 0.0f;
            #pragma unroll
            for (int t = 0; t < 8; t++) {
                sc[mt][t][0] = __expf(sc[mt][t][0] - mA2);
                sc[mt][t][1] = __expf(sc[mt][t][1] - mA2);
                sc[mt][t][2] = __expf(sc[mt][t][2] - mB2);
                sc[mt][t][3] = __expf(sc[mt][t][3] - mB2);
                sA += sc[mt][t][0] + sc[mt][t][1];
                sB += sc[mt][t][2] + sc[mt][t][3];
            }
            #pragma unroll
            for (int o = 1; o <= 2; o <<= 1) {
                sA += __shfl_xor_sync(0xffffffffu, sA, o);
                sB += __shfl_xor_sync(0xffffffffu, sB, o);
            }
            mA[mt] = mA2; mB[mt] = mB2;
            lA[mt] = lA[mt] * alA + sA;
            lB[mt] = lB[mt] * alB + sB;

            #pragma unroll
            for (int t = 0; t < 8; t++) {
                oc[mt][t][0] *= alA; oc[mt][t][1] *= alA;
                oc[mt][t][2] *= alB; oc[mt][t][3] *= alB;
            }
        }

        #pragma unroll
        for (int kk = 0; kk < 4; kk++) {
            uint32_t vb[8][2];
            #pragma unroll
            for (int np = 0; np < 4; np++)
                ldm_x4_t(vb[2 * np][0], vb[2 * np][1], vb[2 * np + 1][0], vb[2 * np + 1][1],
                         V + (kk * 16 + vt_row) * AT_LD + np * 16 + vt_co);
            #pragma unroll
            for (int mt = 0; mt < 2; mt++) {
                uint32_t ap[4];
                ap[0] = pack_h2(sc[mt][2 * kk][0],     sc[mt][2 * kk][1]);
                ap[1] = pack_h2(sc[mt][2 * kk][2],     sc[mt][2 * kk][3]);
                ap[2] = pack_h2(sc[mt][2 * kk + 1][0], sc[mt][2 * kk + 1][1]);
                ap[3] = pack_h2(sc[mt][2 * kk + 1][2], sc[mt][2 * kk + 1][3]);
                #pragma unroll
                for (int nt = 0; nt < 8; nt++)
                    mma_f16(oc[mt][nt], ap, vb[nt][0], vb[nt][1]);
            }
        }
    }

    #pragma unroll
    for (int mt = 0; mt < 2; mt++) {
        const float iA = 1.0f / lA[mt];
        const float iB = 1.0f / lB[mt];
        __half* ob = out + (size_t)(b * SEQ + qt * BQ + w * 32 + mt * 16 + g) * CH + h * 64 + c2;
        #pragma unroll
        for (int t = 0; t < 8; t++) {
            *reinterpret_cast<__half2*>(ob + t * 8) =
                __floats2half2_rn(oc[mt][t][0] * iA, oc[mt][t][1] * iA);
            *reinterpret_cast<__half2*>(ob + 8 * CH + t * 8) =
                __floats2half2_rn(oc[mt][t][2] * iB, oc[mt][t][3] * iB);
        }
    }
}

// ---------------- launch ----------------
extern "C" void kernel_launch(void* const* d_in, const int* in_sizes, int n_in,
                              void* d_out, int out_size)
{
    const float* x     = (const float*)d_in[0];
    const float* w_qkv = (const float*)d_in[1];
    const float* w_out = (const float*)d_in[2];
    float* out = (float*)d_out;

    __half *qkvh, *attnh, *xh, *wqkvh, *wouth;
    cudaGetSymbolAddress((void**)&qkvh,  g_qkvh);
    cudaGetSymbolAddress((void**)&attnh, g_attnh);
    cudaGetSymbolAddress((void**)&xh,    g_xh);
    cudaGetSymbolAddress((void**)&wqkvh, g_wqkvh);
    cudaGetSymbolAddress((void**)&wouth, g_wouth);

    cudaFuncSetAttribute(gemm_f16_kernel<true, 128>,
                         cudaFuncAttributeMaxDynamicSharedMemorySize, GEMM_SMEM_128);
    cudaFuncSetAttribute(gemm_f16_kernel<false, 64>,
                         cudaFuncAttributeMaxDynamicSharedMemorySize, GEMM_SMEM_64);
    cudaFuncSetAttribute(attn_kernel, cudaFuncAttributeMaxDynamicSharedMemorySize, AT_SMEM_BYTES);

    // 0) single fused fp32->fp16 pre-pass (x, w_qkv, w_out; no transposes)
    f2h3_kernel<<<512, 256>>>(
        (const float4*)x,     (__half2*)xh,    (ROWS * CH) / 4,
        (const float4*)w_qkv, (__half2*)wqkvh, (CH * C3) / 4,
        (const float4*)w_out, (__half2*)wouth, (CH * CH) / 4);

    // 1) qkv = x @ w_qkv  -> fp16 [8192 x 3072]
    gemm_f16_kernel<true, 128><<<dim3(C3 / 128, ROWS / 128), 128, GEMM_SMEM_128>>>(
        xh, wqkvh, qkvh, C3, CH);

    // 2) flash attention -> fp16
    attn_kernel<<<dim3(SEQ / BQ, BATCH * NHEAD), 128, AT_SMEM_BYTES>>>(qkvh, attnh);

    // 3) out = attn @ w_out -> fp32 [8192 x 1024], 64-col tiles for tail balance
    gemm_f16_kernel<false, 64><<<dim3(CH / 64, ROWS / 128), 128, GEMM_SMEM_64>>>(
        attnh, wouth, out, CH, CH);
}

// round 11
// speedup vs baseline: 6.5443x; 1.0433x over previous
#include <cuda_runtime.h>
#include <cuda_fp16.h>
#include <math.h>
#include <stdint.h>

#define BATCH 4
#define SEQ   2048
#define CH    1024
#define NHEAD 16
#define DK    64
#define C3    3072
#define ROWS  (BATCH*SEQ)   // 8192

// ---------------- scratch ----------------
__device__ __align__(16) __half g_qkvh[(size_t)ROWS * C3];
__device__ __align__(16) __half g_attnh[(size_t)ROWS * CH];
__device__ __align__(16) __half g_xh[(size_t)ROWS * CH];
__device__ __align__(16) __half g_wqkvh[(size_t)CH * C3];   // [K,N] natural layout
__device__ __align__(16) __half g_wouth[(size_t)CH * CH];   // [K,N] natural layout

// ---------------- helpers ----------------
__device__ __forceinline__ void cp_async16(void* smem_dst, const void* gmem_src) {
    unsigned s = (unsigned)__cvta_generic_to_shared(smem_dst);
    asm volatile("cp.async.cg.shared.global [%0], [%1], 16;\n" :: "r"(s), "l"(gmem_src));
}
__device__ __forceinline__ void cp_commit() {
    asm volatile("cp.async.commit_group;\n" ::);
}
template<int N>
__device__ __forceinline__ void cp_wait() {
    asm volatile("cp.async.wait_group %0;\n" :: "n"(N));
}
__device__ __forceinline__ void mma_f16(float c[4], const uint32_t a[4], uint32_t b0, uint32_t b1) {
    asm volatile(
        "mma.sync.aligned.m16n8k16.row.col.f32.f16.f16.f32 "
        "{%0,%1,%2,%3}, {%4,%5,%6,%7}, {%8,%9}, {%0,%1,%2,%3};"
        : "+f"(c[0]), "+f"(c[1]), "+f"(c[2]), "+f"(c[3])
        : "r"(a[0]), "r"(a[1]), "r"(a[2]), "r"(a[3]), "r"(b0), "r"(b1));
}
__device__ __forceinline__ uint32_t pack_h2(float x, float y) {
    __half2 h = __floats2half2_rn(x, y);
    return *reinterpret_cast<uint32_t*>(&h);
}
__device__ __forceinline__ uint32_t h2exp2_u(uint32_t d2) {
    uint32_t r;
    asm("ex2.approx.f16x2 %0, %1;" : "=r"(r) : "r"(d2));
    return r;
}
__device__ __forceinline__ float ex2f_(float x) {
    float r;
    asm("ex2.approx.f32 %0, %1;" : "=f"(r) : "f"(x));
    return r;
}
__device__ __forceinline__ void ldm_x4(uint32_t& r0, uint32_t& r1, uint32_t& r2, uint32_t& r3,
                                       const __half* p) {
    uint32_t addr = (uint32_t)__cvta_generic_to_shared(p);
    asm volatile("ldmatrix.sync.aligned.m8n8.x4.shared.b16 {%0,%1,%2,%3}, [%4];"
        : "=r"(r0), "=r"(r1), "=r"(r2), "=r"(r3) : "r"(addr));
}
__device__ __forceinline__ void ldm_x4_t(uint32_t& r0, uint32_t& r1, uint32_t& r2, uint32_t& r3,
                                         const __half* p) {
    uint32_t addr = (uint32_t)__cvta_generic_to_shared(p);
    asm volatile("ldmatrix.sync.aligned.m8n8.x4.trans.shared.b16 {%0,%1,%2,%3}, [%4];"
        : "=r"(r0), "=r"(r1), "=r"(r2), "=r"(r3) : "r"(addr));
}

// ---------------- fused pre-pass: fp32 -> fp16 for x, w_qkv, w_out ----------------
__global__ void f2h3_kernel(const float4* __restrict__ a, __half2* __restrict__ ah, int na,
                            const float4* __restrict__ b, __half2* __restrict__ bh, int nb,
                            const float4* __restrict__ c, __half2* __restrict__ ch, int nc)
{
    int i = blockIdx.x * blockDim.x + threadIdx.x;
    const int stride = gridDim.x * blockDim.x;
    const int tot = na + nb + nc;
    for (; i < tot; i += stride) {
        const float4* src;
        __half2* dst;
        int k;
        if (i < na)            { src = a; dst = ah; k = i; }
        else if (i < na + nb)  { src = b; dst = bh; k = i - na; }
        else                   { src = c; dst = ch; k = i - na - nb; }
        float4 v = src[k];
        dst[2 * k]     = __floats2half2_rn(v.x, v.y);
        dst[2 * k + 1] = __floats2half2_rn(v.z, v.w);
    }
}

// ---------------- fp16 GEMM: C[M,N] = A[M,K] @ B[K,N] ----------------
#define GTK 32
#define GALD 40
#define G_ASTG (128 * GALD)           // 5120 halves

template<bool HALF_OUT, int TN>
__global__ void __launch_bounds__(128, 2) gemm_f16_kernel(
    const __half* __restrict__ A, const __half* __restrict__ B,
    void* __restrict__ Cout, int Ntot, int K)
{
    constexpr int WN   = TN / 2;
    constexpr int NT   = WN / 8;
    constexpr int NG   = WN / 16;
    constexpr int BLD  = TN + 8;
    constexpr int BSTG = GTK * BLD;
    constexpr int STG  = G_ASTG + BSTG;

    extern __shared__ __half sh[];
    const int tid = threadIdx.x;
    const int lane = tid & 31;
    const int wid = tid >> 5;
    const int wm = wid & 1;
    const int wn = wid >> 1;
    const int m0 = blockIdx.y * 128;
    const int n0 = blockIdx.x * TN;
    const int KT = K / GTK;
    const int g = lane >> 2;
    const int c2 = 2 * (lane & 3);

    const int a_row = lane & 15;
    const int a_ko  = (lane >> 4) * 8;
    const int vt_row = ((lane >> 3) & 1) * 8 + (lane & 7);
    const int vt_co  = (lane >> 4) * 8;

    auto fill = [&](int buf, int s) {
        __half* As = sh + buf * STG;
        __half* Bs = As + G_ASTG;
        const int k0 = s * GTK;
        #pragma unroll
        for (int j = 0; j < 4; j++) {
            int c = tid + j * 128;
            int row = c >> 2, chh = (c & 3) << 3;
            cp_async16(As + row * GALD + chh, A + (size_t)(m0 + row) * K + k0 + chh);
        }
        #pragma unroll
        for (int j = 0; j < TN / 32; j++) {
            int c = tid + j * 128;
            int row = c / (TN / 8);
            int chh = (c % (TN / 8)) * 8;
            cp_async16(Bs + row * BLD + chh, B + (size_t)(k0 + row) * Ntot + n0 + chh);
        }
    };

    float acc[4][NT][4];
    #pragma unroll
    for (int i = 0; i < 4; i++)
        #pragma unroll
        for (int j = 0; j < NT; j++)
            #pragma unroll
            for (int e = 0; e < 4; e++) acc[i][j][e] = 0.0f;

    fill(0, 0); cp_commit();
    fill(1, 1); cp_commit();
    fill(2, 2); cp_commit();

    for (int s = 0; s < KT; s++) {
        cp_wait<2>();
        __syncthreads();
        if (s + 3 < KT) fill((s + 3) & 3, s + 3);
        cp_commit();

        const __half* As = sh + (s & 3) * STG;
        const __half* Bs = As + G_ASTG;

        #pragma unroll
        for (int kk = 0; kk < 2; kk++) {
            uint32_t a[4][4];
            #pragma unroll
            for (int mt = 0; mt < 4; mt++)
                ldm_x4(a[mt][0], a[mt][1], a[mt][2], a[mt][3],
                       As + (wm * 64 + mt * 16 + a_row) * GALD + kk * 16 + a_ko);

            uint32_t bf[NT][2];
            #pragma unroll
            for (int ng = 0; ng < NG; ng++)
                ldm_x4_t(bf[2 * ng][0], bf[2 * ng][1], bf[2 * ng + 1][0], bf[2 * ng + 1][1],
                         Bs + (kk * 16 + vt_row) * BLD + wn * WN + ng * 16 + vt_co);

            #pragma unroll
            for (int mt = 0; mt < 4; mt++)
                #pragma unroll
                for (int nt = 0; nt < NT; nt++)
                    mma_f16(acc[mt][nt], a[mt], bf[nt][0], bf[nt][1]);
        }
    }

    #pragma unroll
    for (int mt = 0; mt < 4; mt++) {
        #pragma unroll
        for (int nt = 0; nt < NT; nt++) {
            const int row = m0 + wm * 64 + mt * 16 + g;
            const int col = n0 + wn * WN + nt * 8 + c2;
            if (HALF_OUT) {
                __half* Ch = (__half*)Cout;
                *reinterpret_cast<__half2*>(Ch + (size_t)row * Ntot + col) =
                    __floats2half2_rn(acc[mt][nt][0], acc[mt][nt][1]);
                *reinterpret_cast<__half2*>(Ch + (size_t)(row + 8) * Ntot + col) =
                    __floats2half2_rn(acc[mt][nt][2], acc[mt][nt][3]);
            } else {
                float* Cf = (float*)Cout;
                *reinterpret_cast<float2*>(Cf + (size_t)row * Ntot + col) =
                    make_float2(acc[mt][nt][0], acc[mt][nt][1]);
                *reinterpret_cast<float2*>(Cf + (size_t)(row + 8) * Ntot + col) =
                    make_float2(acc[mt][nt][2], acc[mt][nt][3]);
            }
        }
    }
}

#define GEMM_SMEM_128 ((G_ASTG + GTK * 136) * 2 * 4)   // 75776 bytes

// ---------------- Flash attention: 128 q-rows, 4 warps x 32 rows ----------------
// h2exp softmax (log2 domain), row sums via ones-column in V (9th n-tile).
#define BQ 128
#define AT_LD 88
#define KV_TILE (64 * AT_LD)                        // 5632 halves
#define AT_BUF (2 * KV_TILE)                        // 11264 halves per stage
#define AT_SMEM_HALVES (3 * AT_BUF + BQ * AT_LD)    // 45056
#define AT_SMEM_BYTES (AT_SMEM_HALVES * 2)          // 90112
#define L2E 1.4426950408889634f

__global__ void __launch_bounds__(128, 2) attn_kernel(
    const __half* __restrict__ qkvh, __half* __restrict__ out)
{
    extern __shared__ __half smh[];
    const int tid = threadIdx.x;
    const int lane = tid & 31;
    const int w = tid >> 5;
    const int g = lane >> 2;
    const int c2 = 2 * (lane & 3);
    const int qt = gridDim.x - 1 - blockIdx.x;
    const int bh = blockIdx.y;
    const int b = bh >> 4;
    const int h = bh & 15;

    const int a_row = lane & 15;
    const int a_ko  = (lane >> 4) * 8;
    const int b_row = ((lane >> 4) * 8) + (lane & 7);
    const int b_ko  = ((lane >> 3) & 1) * 8;
    const int vt_row = ((lane >> 3) & 1) * 8 + (lane & 7);
    const int vt_co  = (lane >> 4) * 8;

    __half* Qs = smh + 3 * AT_BUF;
    const int NJ = 2 * qt + 2;

    auto fill = [&](int buf, int j) {
        __half* K = smh + buf * AT_BUF;
        __half* V = K + KV_TILE;
        const __half* kg = qkvh + (size_t)(b * SEQ + j * 64) * C3 + CH + h * 64;
        #pragma unroll
        for (int i = 0; i < 4; i++) {
            int f = tid + i * 128;
            int r = f >> 3, ch = (f & 7) << 3;
            const __half* src = kg + (size_t)r * C3 + ch;
            cp_async16(K + r * AT_LD + ch, src);
            cp_async16(V + r * AT_LD + ch, src + CH);
        }
    };

    fill(0, 0); cp_commit();
    if (NJ > 1) fill(1, 1);
    cp_commit();

    // Init V pad columns (64..87) of all 3 buffers: col 64 = 1 (l-column), rest 0.
    for (int idx = tid; idx < 3 * 64 * 24; idx += 128) {
        int bufi = idx / (64 * 24);
        int rr = (idx % (64 * 24)) / 24;
        int cc = idx % 24;
        smh[bufi * AT_BUF + KV_TILE + rr * AT_LD + 64 + cc] =
            (cc == 0) ? __float2half(1.0f) : __float2half(0.0f);
    }

    // Q tile
    {
        const __half* gq = qkvh + (size_t)(b * SEQ + qt * BQ) * C3 + h * 64;
        #pragma unroll
        for (int f = tid; f < 1024; f += 128) {
            int r = f >> 3, ch = (f & 7) << 3;
            *reinterpret_cast<uint4*>(Qs + r * AT_LD + ch) =
                *reinterpret_cast<const uint4*>(gq + (size_t)r * C3 + ch);
        }
    }
    __syncthreads();

    // Q a-fragments, scaled by 1/8 (exact in fp16)
    uint32_t aq[2][4][4];
    {
        const __half2 sc8 = __float2half2_rn(0.125f);
        #pragma unroll
        for (int mt = 0; mt < 2; mt++)
            #pragma unroll
            for (int kk = 0; kk < 4; kk++) {
                ldm_x4(aq[mt][kk][0], aq[mt][kk][1], aq[mt][kk][2], aq[mt][kk][3],
                       Qs + (w * 32 + mt * 16 + a_row) * AT_LD + kk * 16 + a_ko);
                #pragma unroll
                for (int e = 0; e < 4; e++) {
                    __half2 v = *reinterpret_cast<__half2*>(&aq[mt][kk][e]);
                    v = __hmul2(v, sc8);
                    aq[mt][kk][e] = *reinterpret_cast<uint32_t*>(&v);
                }
            }
    }

    // oc[mt][0..7] = O accumulators (cols 0..63); oc[mt][8] = l column (col 64)
    float oc[2][9][4];
    #pragma unroll
    for (int mt = 0; mt < 2; mt++)
        #pragma unroll
        for (int t = 0; t < 9; t++)
            #pragma unroll
            for (int e = 0; e < 4; e++) oc[mt][t][e] = 0.0f;
    float mA[2] = {-INFINITY, -INFINITY}, mB[2] = {-INFINITY, -INFINITY};

    const int qrow0 = qt * BQ + w * 32;

    int buf = 0;
    for (int j = 0; j < NJ; j++) {
        cp_wait<1>();
        __syncthreads();
        if (j + 2 < NJ) fill((buf + 2 >= 3) ? buf - 1 : buf + 2, j + 2);
        cp_commit();

        const int jbase = j * 64;
        const __half* K = smh + buf * AT_BUF;
        const __half* V = K + KV_TILE;
        buf = (buf == 2) ? 0 : buf + 1;

        if (jbase > qrow0 + 31) continue;   // warp-uniform skip

        // ---- S = Q*K^T ----
        float sc[2][8][4];
        #pragma unroll
        for (int mt = 0; mt < 2; mt++)
            #pragma unroll
            for (int t = 0; t < 8; t++)
                #pragma unroll
                for (int e = 0; e < 4; e++) sc[mt][t][e] = 0.0f;

        #pragma unroll
        for (int kk = 0; kk < 4; kk++) {
            uint32_t kb[8][2];
            #pragma unroll
            for (int np = 0; np < 4; np++)
                ldm_x4(kb[2 * np][0], kb[2 * np][1], kb[2 * np + 1][0], kb[2 * np + 1][1],
                       K + (np * 16 + b_row) * AT_LD + kk * 16 + b_ko);
            #pragma unroll
            for (int mt = 0; mt < 2; mt++)
                #pragma unroll
                for (int nt = 0; nt < 8; nt++)
                    mma_f16(sc[mt][nt], aq[mt][kk], kb[nt][0], kb[nt][1]);
        }

        // ---- causal mask ----
        if (jbase + 63 > qrow0) {
            #pragma unroll
            for (int mt = 0; mt < 2; mt++) {
                const int qA = qrow0 + mt * 16 + g;
                #pragma unroll
                for (int t = 0; t < 8; t++) {
                    int cc0 = jbase + t * 8 + c2;
                    int cc1 = cc0 + 1;
                    if (cc0 > qA)     sc[mt][t][0] = -INFINITY;
                    if (cc1 > qA)     sc[mt][t][1] = -INFINITY;
                    if (cc0 > qA + 8) sc[mt][t][2] = -INFINITY;
                    if (cc1 > qA + 8) sc[mt][t][3] = -INFINITY;
                }
            }
        }

        // ---- softmax: running max + h2exp in log2 domain; no explicit sums ----
        uint32_t sp[2][8][2];
        #pragma unroll
        for (int mt = 0; mt < 2; mt++) {
            float mxA = -INFINITY, mxB = -INFINITY;
            #pragma unroll
            for (int t = 0; t < 8; t++) {
                mxA = fmaxf(mxA, fmaxf(sc[mt][t][0], sc[mt][t][1]));
                mxB = fmaxf(mxB, fmaxf(sc[mt][t][2], sc[mt][t][3]));
            }
            #pragma unroll
            for (int o = 1; o <= 2; o <<= 1) {
                mxA = fmaxf(mxA, __shfl_xor_sync(0xffffffffu, mxA, o));
                mxB = fmaxf(mxB, __shfl_xor_sync(0xffffffffu, mxB, o));
            }
            const float mA2 = fmaxf(mA[mt], mxA);
            const float mB2 = fmaxf(mB[mt], mxB);
            const float alA = ex2f_((mA[mt] - mA2) * L2E);
            const float alB = ex2f_((mB[mt] - mB2) * L2E);
            mA[mt] = mA2; mB[mt] = mB2;
            const float negA = -mA2 * L2E;
            const float negB = -mB2 * L2E;

            #pragma unroll
            for (int t = 0; t < 8; t++) {
                float d0 = fmaf(sc[mt][t][0], L2E, negA);
                float d1 = fmaf(sc[mt][t][1], L2E, negA);
                float d2 = fmaf(sc[mt][t][2], L2E, negB);
                float d3 = fmaf(sc[mt][t][3], L2E, negB);
                sp[mt][t][0] = h2exp2_u(pack_h2(d0, d1));
                sp[mt][t][1] = h2exp2_u(pack_h2(d2, d3));
            }
            #pragma unroll
            for (int t = 0; t < 9; t++) {
                oc[mt][t][0] *= alA; oc[mt][t][1] *= alA;
                oc[mt][t][2] *= alB; oc[mt][t][3] *= alB;
            }
        }

        // ---- O (+l) += P * [V | 1] : 9 n-tiles, ldmatrix.trans ----
        #pragma unroll
        for (int kk = 0; kk < 4; kk++) {
            uint32_t vb[10][2];
            #pragma unroll
            for (int np = 0; np < 5; np++)
                ldm_x4_t(vb[2 * np][0], vb[2 * np][1], vb[2 * np + 1][0], vb[2 * np + 1][1],
                         V + (kk * 16 + vt_row) * AT_LD + np * 16 + vt_co);
            #pragma unroll
            for (int mt = 0; mt < 2; mt++) {
                uint32_t ap[4];
                ap[0] = sp[mt][2 * kk][0];
                ap[1] = sp[mt][2 * kk][1];
                ap[2] = sp[mt][2 * kk + 1][0];
                ap[3] = sp[mt][2 * kk + 1][1];
                #pragma unroll
                for (int nt = 0; nt < 9; nt++)
                    mma_f16(oc[mt][nt], ap, vb[nt][0], vb[nt][1]);
            }
        }
    }

    // ---- epilogue: l lives in oc[mt][8][0]/[2] at tig==0; broadcast in quad ----
    #pragma unroll
    for (int mt = 0; mt < 2; mt++) {
        const float lA = __shfl_sync(0xffffffffu, oc[mt][8][0], lane & ~3);
        const float lB = __shfl_sync(0xffffffffu, oc[mt][8][2], lane & ~3);
        const float iA = 1.0f / lA;
        const float iB = 1.0f / lB;
        __half* ob = out + (size_t)(b * SEQ + qt * BQ + w * 32 + mt * 16 + g) * CH + h * 64 + c2;
        #pragma unroll
        for (int t = 0; t < 8; t++) {
            *reinterpret_cast<__half2*>(ob + t * 8) =
                __floats2half2_rn(oc[mt][t][0] * iA, oc[mt][t][1] * iA);
            *reinterpret_cast<__half2*>(ob + 8 * CH + t * 8) =
                __floats2half2_rn(oc[mt][t][2] * iB, oc[mt][t][3] * iB);
        }
    }
}

// ---------------- launch ----------------
extern "C" void kernel_launch(void* const* d_in, const int* in_sizes, int n_in,
                              void* d_out, int out_size)
{
    const float* x     = (const float*)d_in[0];
    const float* w_qkv = (const float*)d_in[1];
    const float* w_out = (const float*)d_in[2];
    float* out = (float*)d_out;

    __half *qkvh, *attnh, *xh, *wqkvh, *wouth;
    cudaGetSymbolAddress((void**)&qkvh,  g_qkvh);
    cudaGetSymbolAddress((void**)&attnh, g_attnh);
    cudaGetSymbolAddress((void**)&xh,    g_xh);
    cudaGetSymbolAddress((void**)&wqkvh, g_wqkvh);
    cudaGetSymbolAddress((void**)&wouth, g_wouth);

    cudaFuncSetAttribute(gemm_f16_kernel<true, 128>,
                         cudaFuncAttributeMaxDynamicSharedMemorySize, GEMM_SMEM_128);
    cudaFuncSetAttribute(gemm_f16_kernel<false, 128>,
                         cudaFuncAttributeMaxDynamicSharedMemorySize, GEMM_SMEM_128);
    cudaFuncSetAttribute(attn_kernel, cudaFuncAttributeMaxDynamicSharedMemorySize, AT_SMEM_BYTES);

    // 0) single fused fp32->fp16 pre-pass
    f2h3_kernel<<<512, 256>>>(
        (const float4*)x,     (__half2*)xh,    (ROWS * CH) / 4,
        (const float4*)w_qkv, (__half2*)wqkvh, (CH * C3) / 4,
        (const float4*)w_out, (__half2*)wouth, (CH * CH) / 4);

    // 1) qkv = x @ w_qkv  -> fp16 [8192 x 3072]
    gemm_f16_kernel<true, 128><<<dim3(C3 / 128, ROWS / 128), 128, GEMM_SMEM_128>>>(
        xh, wqkvh, qkvh, C3, CH);

    // 2) flash attention -> fp16
    attn_kernel<<<dim3(SEQ / BQ, BATCH * NHEAD), 128, AT_SMEM_BYTES>>>(qkvh, attnh);

    // 3) out = attn @ w_out -> fp32 [8192 x 1024]
    gemm_f16_kernel<false, 128><<<dim3(CH / 128, ROWS / 128), 128, GEMM_SMEM_128>>>(
        attnh, wouth, out, CH, CH);
}